// round 11
// baseline (speedup 1.0000x reference)
#include <cuda_runtime.h>
#include <cstdint>

#define NMAX 50000
#define EMAX 800000

// Scratch (device globals; no allocation allowed)
__device__ __align__(256) float g_h[2][(size_t)NMAX * 64];
__device__ __align__(256) int   g_cnt[NMAX];
__device__ __align__(256) int   g_fill[NMAX];
__device__ __align__(256) int   g_rowptr[NMAX + 1];
__device__ __align__(256) int   g_csr_src[EMAX];
__device__ __align__(256) float g_t[NMAX];
__device__ __align__(256) int   g_bsum[256];
__device__ __align__(256) int   g_bscan[256];
__device__ int g_is64;

// ---------------- mma.sync tf32 helpers (compute_100-safe, sm_80+) ----------------
__device__ __forceinline__ uint32_t f2tf32(float x) {
    uint32_t r;
    asm("cvt.rna.tf32.f32 %0, %1;" : "=r"(r) : "f"(x));
    return r;
}
__device__ __forceinline__ void mma_tf32(float& d0, float& d1, float& d2, float& d3,
                                         uint32_t a0, uint32_t a1, uint32_t a2, uint32_t a3,
                                         uint32_t b0, uint32_t b1) {
    asm volatile(
        "mma.sync.aligned.m16n8k8.row.col.f32.tf32.tf32.f32 "
        "{%0,%1,%2,%3}, {%4,%5,%6,%7}, {%8,%9}, {%0,%1,%2,%3};"
        : "+f"(d0), "+f"(d1), "+f"(d2), "+f"(d3)
        : "r"(a0), "r"(a1), "r"(a2), "r"(a3), "r"(b0), "r"(b1));
}

// ---------------- zero + edge dtype detection (fused) ----------------
__global__ void zero_start(const int* ei32, int E, int n) {
    int i = blockIdx.x * blockDim.x + threadIdx.x;
    int stride = gridDim.x * blockDim.x;
    for (int j = i; j < n; j += stride) { g_cnt[j] = 0; g_fill[j] = 0; }
    if (i == 0) {
        int all0 = 1;
        for (int k = 0; k < 64; k++) {
            long long p = 1 + 2 * ((long long)k * (E / 2 - 1) / 64);
            if (ei32[p] != 0) { all0 = 0; break; }
        }
        g_is64 = all0;
    }
}

__device__ __forceinline__ int load_idx(const void* ei, int E, int half, int e, int is64, int n) {
    int v;
    if (is64) v = (int)((const long long*)ei)[(size_t)half * E + e];
    else      v = ((const int*)ei)[(size_t)half * E + e];
    return min(max(v, 0), n - 1);
}

__global__ void count_kernel(const void* __restrict__ ei, int E, int n) {
    int e = blockIdx.x * blockDim.x + threadIdx.x;
    if (e >= E) return;
    int d = load_idx(ei, E, 1, e, g_is64, n);
    atomicAdd(&g_cnt[d], 1);
}

// ---------------- 3-phase parallel exclusive scan ----------------
__global__ void __launch_bounds__(256) scan_partial(int n) {
    int t = threadIdx.x;
    int i = blockIdx.x * 256 + t;
    int v = (i < n) ? g_cnt[i] : 0;
    int w = v;
#pragma unroll
    for (int off = 16; off >= 1; off >>= 1) w += __shfl_xor_sync(0xffffffffu, w, off);
    __shared__ int red[8];
    if ((t & 31) == 0) red[t >> 5] = w;
    __syncthreads();
    if (t == 0) {
        int s = 0;
#pragma unroll
        for (int k = 0; k < 8; k++) s += red[k];
        g_bsum[blockIdx.x] = s;
    }
}

__global__ void __launch_bounds__(256) scan_bsum(int nb, int n) {
    __shared__ int s[256];
    int t = threadIdx.x;
    int v = (t < nb) ? g_bsum[t] : 0;
    s[t] = v;
    __syncthreads();
#pragma unroll
    for (int off = 1; off < 256; off <<= 1) {
        int a = s[t];
        int b = (t >= off) ? s[t - off] : 0;
        __syncthreads();
        s[t] = a + b;
        __syncthreads();
    }
    if (t < nb) g_bscan[t] = s[t] - v;
    if (t == nb - 1) g_rowptr[n] = s[t];
}

__global__ void __launch_bounds__(256) scan_final(int n) {
    int t = threadIdx.x;
    int lane = t & 31;
    int wid = t >> 5;
    int i = blockIdx.x * 256 + t;
    int v = (i < n) ? g_cnt[i] : 0;
    int inc = v;
#pragma unroll
    for (int off = 1; off < 32; off <<= 1) {
        int u = __shfl_up_sync(0xffffffffu, inc, off);
        if (lane >= off) inc += u;
    }
    __shared__ int wsum[8];
    if (lane == 31) wsum[wid] = inc;
    __syncthreads();
    if (t == 0) {
        int s = 0;
#pragma unroll
        for (int k = 0; k < 8; k++) { int u = wsum[k]; wsum[k] = s; s += u; }
    }
    __syncthreads();
    if (i < n) g_rowptr[i] = g_bscan[blockIdx.x] + wsum[wid] + inc - v;
}

__global__ void fill_kernel(const void* __restrict__ ei, int E, int n) {
    int e = blockIdx.x * blockDim.x + threadIdx.x;
    if (e >= E) return;
    int is64 = g_is64;
    int s = load_idx(ei, E, 0, e, is64, n);
    int d = load_idx(ei, E, 1, e, is64, n);
    int pos = g_rowptr[d] + atomicAdd(&g_fill[d], 1);
    if (pos < EMAX) g_csr_src[pos] = s;
}

// ---------------- Fused layer CIN=64: gather + mma.sync tf32 (3xTF32) ----------------
// Block 256 thr (8 warps), M=64 rows/block.
// A[64x128] = [agg|h] fp32 in smem (stride 132). B[64x128] = [Wl;Wr]^T fp32 (stride 132).
// Warp (wr=warp&3, wc=warp>>2) -> rows wr*16..+16, cols wc*32..+32.
// 16 K-steps of k=8; per n-tile 3 MMAs: Ahi*Bhi + Alo*Bhi + Ahi*Blo (~fp32 accuracy).
#define TC_ROWS 64
#define TC_LA 132
#define TC_DSMEM (2 * 64 * TC_LA * 4)

template <bool FT>
__global__ void __launch_bounds__(256) fused64tc(
    int in_idx, int out_idx,
    const float* __restrict__ Wl, const float* __restrict__ bl,
    const float* __restrict__ Wr, const float* __restrict__ Wl4,
    int n)
{
    extern __shared__ __align__(16) float dyn[];
    float* a_s = dyn;                 // 64 x 132
    float* b_s = a_s + 64 * TC_LA;    // 64 x 132 (n-major: b_s[nn][kk])
    __shared__ float bl_s[64];
    __shared__ float wl4_s[64];
    __shared__ float s_p[64];

    const float* hin = g_h[in_idx];
    float* hout = g_h[out_idx];

    int tid = threadIdx.x;
    int base = blockIdx.x * TC_ROWS;
    int warp = tid >> 5;
    int lane = tid & 31;

    // B tile: b_s[nn][kk] = (kk<64 ? Wl[kk][nn] : Wr[kk-64][nn])
    for (int i = tid; i < 64 * 128; i += 256) {
        int nn = i & 63;
        int kk = i >> 6;
        float v = (kk < 64) ? Wl[kk * 64 + nn] : Wr[(kk - 64) * 64 + nn];
        b_s[nn * TC_LA + kk] = v;
    }
    if (tid < 64) {
        bl_s[tid] = bl[tid];
        if (FT) wl4_s[tid] = Wl4[tid];
    }

    // Phase 1: gather (warp per node, 8 nodes per warp)
#pragma unroll
    for (int q = 0; q < 8; q++) {
        int r = warp * 8 + q;
        int row = base + r;
        float2 acc = make_float2(0.f, 0.f);
        if (row < n) {
            int start = g_rowptr[row];
            int end = g_rowptr[row + 1];
            for (int j = start; j < end; j += 32) {
                int m = min(32, end - j);
                int eid = (lane < m) ? g_csr_src[j + lane] : 0;
#pragma unroll
                for (int k = 0; k < 32; k += 8) {
                    if (k >= m) break;
                    float2 v[8];
#pragma unroll
                    for (int u = 0; u < 8; u++) {
                        int s = __shfl_sync(0xffffffffu, eid, k + u);
                        if (k + u < m)
                            v[u] = *(const float2*)(hin + (size_t)s * 64 + 2 * lane);
                        else
                            v[u] = make_float2(0.f, 0.f);
                    }
#pragma unroll
                    for (int u = 0; u < 8; u++) { acc.x += v[u].x; acc.y += v[u].y; }
                }
            }
            float inv = 1.0f / (float)max(end - start, 1);
            acc.x *= inv; acc.y *= inv;
            float2 hv = *(const float2*)(hin + (size_t)row * 64 + 2 * lane);
            *(float2*)&a_s[r * TC_LA + 64 + 2 * lane] = hv;
        } else {
            *(float2*)&a_s[r * TC_LA + 64 + 2 * lane] = make_float2(0.f, 0.f);
        }
        *(float2*)&a_s[r * TC_LA + 2 * lane] = acc;
    }
    __syncthreads();

    // Phase 2: tensor-core GEMM.
    int wr = warp & 3;
    int wc = warp >> 2;
    int g = lane >> 2;       // 0..7
    int t4 = lane & 3;       // 0..3
    int ar0 = wr * 16 + g;   // fragment rows ar0, ar0+8

    float d[4][4];
#pragma unroll
    for (int nt = 0; nt < 4; nt++)
#pragma unroll
        for (int c = 0; c < 4; c++) d[nt][c] = 0.f;

#pragma unroll
    for (int ks = 0; ks < 16; ks++) {
        int k0 = ks * 8;
        // A fragment (fp32 -> hi/lo tf32)
        float af[4];
        af[0] = a_s[ar0 * TC_LA + k0 + t4];
        af[1] = a_s[(ar0 + 8) * TC_LA + k0 + t4];
        af[2] = a_s[ar0 * TC_LA + k0 + t4 + 4];
        af[3] = a_s[(ar0 + 8) * TC_LA + k0 + t4 + 4];
        uint32_t ah[4], al[4];
#pragma unroll
        for (int i = 0; i < 4; i++) {
            ah[i] = f2tf32(af[i]);
            al[i] = f2tf32(af[i] - __uint_as_float(ah[i]));
        }
#pragma unroll
        for (int nt = 0; nt < 4; nt++) {
            int nn = wc * 32 + nt * 8 + g;
            float bf0 = b_s[nn * TC_LA + k0 + t4];
            float bf1 = b_s[nn * TC_LA + k0 + t4 + 4];
            uint32_t bh0 = f2tf32(bf0), bh1 = f2tf32(bf1);
            uint32_t bl0 = f2tf32(bf0 - __uint_as_float(bh0));
            uint32_t bl1 = f2tf32(bf1 - __uint_as_float(bh1));
            mma_tf32(d[nt][0], d[nt][1], d[nt][2], d[nt][3], ah[0], ah[1], ah[2], ah[3], bh0, bh1);
            mma_tf32(d[nt][0], d[nt][1], d[nt][2], d[nt][3], al[0], al[1], al[2], al[3], bh0, bh1);
            mma_tf32(d[nt][0], d[nt][1], d[nt][2], d[nt][3], ah[0], ah[1], ah[2], ah[3], bl0, bl1);
        }
    }

    // Epilogue: bias + relu + store. D tile (16x8): c0:(g,2t) c1:(g,2t+1) c2:(g+8,2t) c3:(g+8,2t+1)
    int row0 = base + wr * 16 + g;
    int row1 = row0 + 8;
    float p0 = 0.f, p1 = 0.f;
#pragma unroll
    for (int nt = 0; nt < 4; nt++) {
        int c = wc * 32 + nt * 8 + 2 * t4;
        float v0 = fmaxf(d[nt][0] + bl_s[c], 0.f);
        float v1 = fmaxf(d[nt][1] + bl_s[c + 1], 0.f);
        float v2 = fmaxf(d[nt][2] + bl_s[c], 0.f);
        float v3 = fmaxf(d[nt][3] + bl_s[c + 1], 0.f);
        if (row0 < n) *(float2*)(hout + (size_t)row0 * 64 + c) = make_float2(v0, v1);
        if (row1 < n) *(float2*)(hout + (size_t)row1 * 64 + c) = make_float2(v2, v3);
        if (FT) {
            p0 += v0 * wl4_s[c] + v1 * wl4_s[c + 1];
            p1 += v2 * wl4_s[c] + v3 * wl4_s[c + 1];
        }
    }

    if (FT) {
        // reduce over t4 (4 lanes) -> sum over this warp's 32 cols
        p0 += __shfl_xor_sync(0xffffffffu, p0, 1);
        p0 += __shfl_xor_sync(0xffffffffu, p0, 2);
        p1 += __shfl_xor_sync(0xffffffffu, p1, 1);
        p1 += __shfl_xor_sync(0xffffffffu, p1, 2);
        int r0 = wr * 16 + g;
        if (wc == 0 && t4 == 0) { s_p[r0] = p0; s_p[r0 + 8] = p1; }
        __syncthreads();
        if (wc == 1 && t4 == 0) {
            if (row0 < n) g_t[row0] = p0 + s_p[r0];
            if (row1 < n) g_t[row1] = p1 + s_p[r0 + 8];
        }
    }
}

// ---------------- Fused layer 0: CIN=13 (FFMA path) ----------------
__global__ void __launch_bounds__(256) fused13(
    const float* __restrict__ x,
    const float* __restrict__ Wl, const float* __restrict__ bl,
    const float* __restrict__ Wr, int n)
{
    constexpr int ROWS = 32;
    constexpr int L = 28;
    __shared__ __align__(16) float w_s[2 * 13 * 64];
    __shared__ __align__(16) float in_s[ROWS * L];
    __shared__ float bl_s[64];

    float* hout = g_h[0];
    int tid = threadIdx.x;
    int base = blockIdx.x * ROWS;
    int warp = tid >> 5;
    int lane = tid & 31;

    for (int i = tid; i < 2 * 13 * 64; i += 256) w_s[i] = (i < 13 * 64) ? Wl[i] : Wr[i - 13 * 64];
    if (tid < 64) bl_s[tid] = bl[tid];

    for (int q = 0; q < 4; q++) {
        int r = warp * 4 + q;
        int row = base + r;
        float acc = 0.f;
        if (row < n) {
            int start = g_rowptr[row];
            int end = g_rowptr[row + 1];
            for (int j = start; j < end; j += 32) {
                int m = min(32, end - j);
                int eid = (lane < m) ? g_csr_src[j + lane] : 0;
#pragma unroll
                for (int k = 0; k < 32; k += 8) {
                    if (k >= m) break;
                    float v[8];
#pragma unroll
                    for (int u = 0; u < 8; u++) {
                        int s = __shfl_sync(0xffffffffu, eid, k + u);
                        v[u] = (lane < 13 && k + u < m) ? __ldg(&x[(size_t)s * 13 + lane]) : 0.f;
                    }
#pragma unroll
                    for (int u = 0; u < 8; u++) acc += v[u];
                }
            }
            float inv = 1.0f / (float)max(end - start, 1);
            if (lane < 13) {
                in_s[r * L + lane] = acc * inv;
                in_s[r * L + 14 + lane] = __ldg(&x[(size_t)row * 13 + lane]);
            }
        } else if (lane < 13) {
            in_s[r * L + lane] = 0.f;
            in_s[r * L + 14 + lane] = 0.f;
        }
    }
    __syncthreads();

    int rr = tid >> 4;
    int cg = tid & 15;
    int j0 = cg * 4;
    const float4* w4 = (const float4*)w_s;

    float a0[4], a1[4];
#pragma unroll
    for (int c = 0; c < 4; c++) { a0[c] = bl_s[j0 + c]; a1[c] = bl_s[j0 + c]; }

    const float* r0p = &in_s[rr * L];
    const float* r1p = &in_s[(rr + 16) * L];
#pragma unroll
    for (int k = 0; k < 13; k++) {
        float4 w = w4[k * 16 + cg];
        float x0 = r0p[k], x1 = r1p[k];
        a0[0] += x0 * w.x; a0[1] += x0 * w.y; a0[2] += x0 * w.z; a0[3] += x0 * w.w;
        a1[0] += x1 * w.x; a1[1] += x1 * w.y; a1[2] += x1 * w.z; a1[3] += x1 * w.w;
    }
#pragma unroll
    for (int k = 0; k < 13; k++) {
        float4 w = w4[(13 + k) * 16 + cg];
        float x0 = r0p[14 + k], x1 = r1p[14 + k];
        a0[0] += x0 * w.x; a0[1] += x0 * w.y; a0[2] += x0 * w.z; a0[3] += x0 * w.w;
        a1[0] += x1 * w.x; a1[1] += x1 * w.y; a1[2] += x1 * w.z; a1[3] += x1 * w.w;
    }

    int row0 = base + rr;
    int row1 = base + rr + 16;
    if (row0 < n) {
#pragma unroll
        for (int c = 0; c < 4; c++) a0[c] = fmaxf(a0[c], 0.f);
        *(float4*)(hout + (size_t)row0 * 64 + j0) = make_float4(a0[0], a0[1], a0[2], a0[3]);
    }
    if (row1 < n) {
#pragma unroll
        for (int c = 0; c < 4; c++) a1[c] = fmaxf(a1[c], 0.f);
        *(float4*)(hout + (size_t)row1 * 64 + j0) = make_float4(a1[0], a1[1], a1[2], a1[3]);
    }
}

// ---------------- Final layer (64 -> 1) ----------------
__global__ void __launch_bounds__(256) final_kernel(
    int in_idx,
    const float* __restrict__ Wr,
    const float* __restrict__ bl,
    float* __restrict__ out, int n)
{
    __shared__ float w[64];
    if (threadIdx.x < 64) w[threadIdx.x] = Wr[threadIdx.x];
    __syncthreads();
    const float* h = g_h[in_idx];

    int gw = (blockIdx.x * blockDim.x + threadIdx.x) >> 5;
    if (gw >= n) return;
    int lane = threadIdx.x & 31;

    int start = g_rowptr[gw];
    int end = g_rowptr[gw + 1];
    float sum = 0.f;
    for (int j = start + lane; j < end; j += 32) sum += __ldg(&g_t[g_csr_src[j]]);

    float inv = 1.0f / (float)max(end - start, 1);
    float2 hv = *(const float2*)(h + (size_t)gw * 64 + 2 * lane);
    float2 wv = *(const float2*)&w[2 * lane];
    float v = sum * inv + hv.x * wv.x + hv.y * wv.y;
#pragma unroll
    for (int off = 16; off >= 1; off >>= 1) v += __shfl_xor_sync(0xffffffffu, v, off);

    if (lane == 0) {
        float z = v + bl[0];
        out[gw] = 1.0f / (1.0f + __expf(-z));
    }
}

// ---------------- launch ----------------
extern "C" void kernel_launch(void* const* d_in, const int* in_sizes, int n_in,
                              void* d_out, int out_size) {
    const float* x = (const float*)d_in[0];
    const void* ei = d_in[1];
    const float* Wl[5]; const float* bl[5]; const float* Wr[5];
    for (int i = 0; i < 5; i++) {
        Wl[i] = (const float*)d_in[2 + 3 * i];
        bl[i] = (const float*)d_in[3 + 3 * i];
        Wr[i] = (const float*)d_in[4 + 3 * i];
    }
    int n = in_sizes[0] / 13;
    int E = in_sizes[1] / 2;
    float* out = (float*)d_out;

    int eb = (E + 255) / 256;
    int nb = (n + 255) / 256;
    int fb13 = (n + 31) / 32;
    int fbtc = (n + TC_ROWS - 1) / TC_ROWS;

    cudaFuncSetAttribute(fused64tc<false>, cudaFuncAttributeMaxDynamicSharedMemorySize, TC_DSMEM);
    cudaFuncSetAttribute(fused64tc<true>,  cudaFuncAttributeMaxDynamicSharedMemorySize, TC_DSMEM);

    zero_start<<<64, 256>>>((const int*)ei, E, n);
    count_kernel<<<eb, 256>>>(ei, E, n);
    scan_partial<<<nb, 256>>>(n);
    scan_bsum<<<1, 256>>>(nb, n);
    scan_final<<<nb, 256>>>(n);
    fill_kernel<<<eb, 256>>>(ei, E, n);

    fused13<<<fb13, 256>>>(x, Wl[0], bl[0], Wr[0], n);                                   // -> g_h[0]
    fused64tc<false><<<fbtc, 256, TC_DSMEM>>>(0, 1, Wl[1], bl[1], Wr[1], Wl[1], n);      // h0 -> h1
    fused64tc<false><<<fbtc, 256, TC_DSMEM>>>(1, 0, Wl[2], bl[2], Wr[2], Wl[2], n);      // h1 -> h0
    fused64tc<true><<<fbtc, 256, TC_DSMEM>>>(0, 1, Wl[3], bl[3], Wr[3], Wl[4], n);       // h0 -> h1, t = h3 @ Wl4
    final_kernel<<<(n * 32 + 255) / 256, 256>>>(1, Wr[4], bl[4], out, n);
}

// round 12
// speedup vs baseline: 1.0783x; 1.0783x over previous
#include <cuda_runtime.h>
#include <cstdint>

#define NMAX 50000
#define EMAX 800000

// Scratch (device globals; no allocation allowed)
__device__ __align__(256) float g_h[2][(size_t)NMAX * 64];
__device__ __align__(256) int   g_cnt[NMAX];
__device__ __align__(256) int   g_fill[NMAX];
__device__ __align__(256) int   g_rowptr[NMAX + 1];
__device__ __align__(256) int   g_csr_src[EMAX];
__device__ __align__(256) float g_t[NMAX];
__device__ __align__(256) int   g_bsum[256];
__device__ __align__(256) int   g_bscan[256];
__device__ int g_is64;

// ---------------- mma.sync tf32 helpers (compute_100-safe, sm_80+) ----------------
__device__ __forceinline__ uint32_t f2tf32(float x) {
    uint32_t r;
    asm("cvt.rna.tf32.f32 %0, %1;" : "=r"(r) : "f"(x));
    return r;
}
__device__ __forceinline__ void mma_tf32(float& d0, float& d1, float& d2, float& d3,
                                         uint32_t a0, uint32_t a1, uint32_t a2, uint32_t a3,
                                         uint32_t b0, uint32_t b1) {
    asm volatile(
        "mma.sync.aligned.m16n8k8.row.col.f32.tf32.tf32.f32 "
        "{%0,%1,%2,%3}, {%4,%5,%6,%7}, {%8,%9}, {%0,%1,%2,%3};"
        : "+f"(d0), "+f"(d1), "+f"(d2), "+f"(d3)
        : "r"(a0), "r"(a1), "r"(a2), "r"(a3), "r"(b0), "r"(b1));
}

// ---------------- zero + edge dtype detection (fused) ----------------
__global__ void zero_start(const int* ei32, int E, int n) {
    int i = blockIdx.x * blockDim.x + threadIdx.x;
    int stride = gridDim.x * blockDim.x;
    for (int j = i; j < n; j += stride) { g_cnt[j] = 0; g_fill[j] = 0; }
    if (i == 0) {
        int all0 = 1;
        for (int k = 0; k < 64; k++) {
            long long p = 1 + 2 * ((long long)k * (E / 2 - 1) / 64);
            if (ei32[p] != 0) { all0 = 0; break; }
        }
        g_is64 = all0;
    }
}

__device__ __forceinline__ int load_idx(const void* ei, int E, int half, int e, int is64, int n) {
    int v;
    if (is64) v = (int)((const long long*)ei)[(size_t)half * E + e];
    else      v = ((const int*)ei)[(size_t)half * E + e];
    return min(max(v, 0), n - 1);
}

__global__ void count_kernel(const void* __restrict__ ei, int E, int n) {
    int e = blockIdx.x * blockDim.x + threadIdx.x;
    if (e >= E) return;
    int d = load_idx(ei, E, 1, e, g_is64, n);
    atomicAdd(&g_cnt[d], 1);
}

// ---------------- 3-phase parallel exclusive scan ----------------
__global__ void __launch_bounds__(256) scan_partial(int n) {
    int t = threadIdx.x;
    int i = blockIdx.x * 256 + t;
    int v = (i < n) ? g_cnt[i] : 0;
    int w = v;
#pragma unroll
    for (int off = 16; off >= 1; off >>= 1) w += __shfl_xor_sync(0xffffffffu, w, off);
    __shared__ int red[8];
    if ((t & 31) == 0) red[t >> 5] = w;
    __syncthreads();
    if (t == 0) {
        int s = 0;
#pragma unroll
        for (int k = 0; k < 8; k++) s += red[k];
        g_bsum[blockIdx.x] = s;
    }
}

__global__ void __launch_bounds__(256) scan_bsum(int nb, int n) {
    __shared__ int s[256];
    int t = threadIdx.x;
    int v = (t < nb) ? g_bsum[t] : 0;
    s[t] = v;
    __syncthreads();
#pragma unroll
    for (int off = 1; off < 256; off <<= 1) {
        int a = s[t];
        int b = (t >= off) ? s[t - off] : 0;
        __syncthreads();
        s[t] = a + b;
        __syncthreads();
    }
    if (t < nb) g_bscan[t] = s[t] - v;
    if (t == nb - 1) g_rowptr[n] = s[t];
}

__global__ void __launch_bounds__(256) scan_final(int n) {
    int t = threadIdx.x;
    int lane = t & 31;
    int wid = t >> 5;
    int i = blockIdx.x * 256 + t;
    int v = (i < n) ? g_cnt[i] : 0;
    int inc = v;
#pragma unroll
    for (int off = 1; off < 32; off <<= 1) {
        int u = __shfl_up_sync(0xffffffffu, inc, off);
        if (lane >= off) inc += u;
    }
    __shared__ int wsum[8];
    if (lane == 31) wsum[wid] = inc;
    __syncthreads();
    if (t == 0) {
        int s = 0;
#pragma unroll
        for (int k = 0; k < 8; k++) { int u = wsum[k]; wsum[k] = s; s += u; }
    }
    __syncthreads();
    if (i < n) g_rowptr[i] = g_bscan[blockIdx.x] + wsum[wid] + inc - v;
}

__global__ void fill_kernel(const void* __restrict__ ei, int E, int n) {
    int e = blockIdx.x * blockDim.x + threadIdx.x;
    if (e >= E) return;
    int is64 = g_is64;
    int s = load_idx(ei, E, 0, e, is64, n);
    int d = load_idx(ei, E, 1, e, is64, n);
    int pos = g_rowptr[d] + atomicAdd(&g_fill[d], 1);
    if (pos < EMAX) g_csr_src[pos] = s;
}

// ---------------- Fused layer CIN=64: float4 gather (2 edges/warp-ld) + tf32 mma ----------------
// Block 256 thr (8 warps), M=64 rows/block.
// Gather: half-warps each own one edge per LDG.128 -> 32 lines in flight per warp.
// A[64x128] = [agg|h] fp32 in smem (stride 132). B[64x128] = [Wl;Wr]^T fp32 (stride 132).
// GEMM: warp (wr=warp&3, wc=warp>>2) -> rows wr*16..+16, cols wc*32..+32, 3xTF32.
#define TC_ROWS 64
#define TC_LA 132
#define TC_DSMEM (2 * 64 * TC_LA * 4)

template <bool FT>
__global__ void __launch_bounds__(256, 3) fused64tc(
    int in_idx, int out_idx,
    const float* __restrict__ Wl, const float* __restrict__ bl,
    const float* __restrict__ Wr, const float* __restrict__ Wl4,
    int n)
{
    extern __shared__ __align__(16) float dyn[];
    float* a_s = dyn;                 // 64 x 132
    float* b_s = a_s + 64 * TC_LA;    // 64 x 132 (n-major: b_s[nn][kk])
    __shared__ float bl_s[64];
    __shared__ float wl4_s[64];
    __shared__ float s_p[64];

    const float* hin = g_h[in_idx];
    float* hout = g_h[out_idx];

    int tid = threadIdx.x;
    int base = blockIdx.x * TC_ROWS;
    int warp = tid >> 5;
    int lane = tid & 31;
    int lane16 = lane & 15;
    int half = lane >> 4;

    // B tile: b_s[nn][kk] = (kk<64 ? Wl[kk][nn] : Wr[kk-64][nn])
    for (int i = tid; i < 64 * 128; i += 256) {
        int nn = i & 63;
        int kk = i >> 6;
        float v = (kk < 64) ? Wl[kk * 64 + nn] : Wr[(kk - 64) * 64 + nn];
        b_s[nn * TC_LA + kk] = v;
    }
    if (tid < 64) {
        bl_s[tid] = bl[tid];
        if (FT) wl4_s[tid] = Wl4[tid];
    }

    // Phase 1: gather (warp per node, 8 nodes per warp). Edge rows read as
    // 16-lane float4: each warp-LDG covers 2 edges (4 cache lines in flight each).
#pragma unroll
    for (int q = 0; q < 8; q++) {
        int r = warp * 8 + q;
        int row = base + r;
        float4 acc = make_float4(0.f, 0.f, 0.f, 0.f);
        if (row < n) {
            int start = g_rowptr[row];
            int end = g_rowptr[row + 1];
            for (int j = start; j < end; j += 32) {
                int m = min(32, end - j);
                int eid = (lane < m) ? g_csr_src[j + lane] : 0;
#pragma unroll
                for (int k = 0; k < 32; k += 16) {
                    if (k >= m) break;
                    float4 v[8];
#pragma unroll
                    for (int u = 0; u < 8; u++) {
                        int idx = k + 2 * u + half;   // <= 31 always
                        int s = __shfl_sync(0xffffffffu, eid, idx);
                        if (idx < m)
                            v[u] = *(const float4*)(hin + (size_t)s * 64 + lane16 * 4);
                        else
                            v[u] = make_float4(0.f, 0.f, 0.f, 0.f);
                    }
#pragma unroll
                    for (int u = 0; u < 8; u++) {
                        acc.x += v[u].x; acc.y += v[u].y; acc.z += v[u].z; acc.w += v[u].w;
                    }
                }
            }
            // combine half-warp partials (both halves end with the full sum)
            acc.x += __shfl_xor_sync(0xffffffffu, acc.x, 16);
            acc.y += __shfl_xor_sync(0xffffffffu, acc.y, 16);
            acc.z += __shfl_xor_sync(0xffffffffu, acc.z, 16);
            acc.w += __shfl_xor_sync(0xffffffffu, acc.w, 16);
            float inv = 1.0f / (float)max(end - start, 1);
            acc.x *= inv; acc.y *= inv; acc.z *= inv; acc.w *= inv;
            float2 hv = *(const float2*)(hin + (size_t)row * 64 + 2 * lane);
            *(float2*)&a_s[r * TC_LA + 64 + 2 * lane] = hv;
        } else {
            *(float2*)&a_s[r * TC_LA + 64 + 2 * lane] = make_float2(0.f, 0.f);
        }
        if (half == 0)
            *(float4*)&a_s[r * TC_LA + lane16 * 4] = acc;
    }
    __syncthreads();

    // Phase 2: tensor-core GEMM (3xTF32 error compensation).
    int wr = warp & 3;
    int wc = warp >> 2;
    int g = lane >> 2;       // 0..7
    int t4 = lane & 3;       // 0..3
    int ar0 = wr * 16 + g;   // fragment rows ar0, ar0+8

    float d[4][4];
#pragma unroll
    for (int nt = 0; nt < 4; nt++)
#pragma unroll
        for (int c = 0; c < 4; c++) d[nt][c] = 0.f;

#pragma unroll
    for (int ks = 0; ks < 16; ks++) {
        int k0 = ks * 8;
        float af[4];
        af[0] = a_s[ar0 * TC_LA + k0 + t4];
        af[1] = a_s[(ar0 + 8) * TC_LA + k0 + t4];
        af[2] = a_s[ar0 * TC_LA + k0 + t4 + 4];
        af[3] = a_s[(ar0 + 8) * TC_LA + k0 + t4 + 4];
        uint32_t ah[4], al[4];
#pragma unroll
        for (int i = 0; i < 4; i++) {
            ah[i] = f2tf32(af[i]);
            al[i] = f2tf32(af[i] - __uint_as_float(ah[i]));
        }
#pragma unroll
        for (int nt = 0; nt < 4; nt++) {
            int nn = wc * 32 + nt * 8 + g;
            float bf0 = b_s[nn * TC_LA + k0 + t4];
            float bf1 = b_s[nn * TC_LA + k0 + t4 + 4];
            uint32_t bh0 = f2tf32(bf0), bh1 = f2tf32(bf1);
            uint32_t bl0 = f2tf32(bf0 - __uint_as_float(bh0));
            uint32_t bl1 = f2tf32(bf1 - __uint_as_float(bh1));
            mma_tf32(d[nt][0], d[nt][1], d[nt][2], d[nt][3], ah[0], ah[1], ah[2], ah[3], bh0, bh1);
            mma_tf32(d[nt][0], d[nt][1], d[nt][2], d[nt][3], al[0], al[1], al[2], al[3], bh0, bh1);
            mma_tf32(d[nt][0], d[nt][1], d[nt][2], d[nt][3], ah[0], ah[1], ah[2], ah[3], bl0, bl1);
        }
    }

    // Epilogue: bias + relu + store.
    int row0 = base + wr * 16 + g;
    int row1 = row0 + 8;
    float p0 = 0.f, p1 = 0.f;
#pragma unroll
    for (int nt = 0; nt < 4; nt++) {
        int c = wc * 32 + nt * 8 + 2 * t4;
        float v0 = fmaxf(d[nt][0] + bl_s[c], 0.f);
        float v1 = fmaxf(d[nt][1] + bl_s[c + 1], 0.f);
        float v2 = fmaxf(d[nt][2] + bl_s[c], 0.f);
        float v3 = fmaxf(d[nt][3] + bl_s[c + 1], 0.f);
        if (row0 < n) *(float2*)(hout + (size_t)row0 * 64 + c) = make_float2(v0, v1);
        if (row1 < n) *(float2*)(hout + (size_t)row1 * 64 + c) = make_float2(v2, v3);
        if (FT) {
            p0 += v0 * wl4_s[c] + v1 * wl4_s[c + 1];
            p1 += v2 * wl4_s[c] + v3 * wl4_s[c + 1];
        }
    }

    if (FT) {
        p0 += __shfl_xor_sync(0xffffffffu, p0, 1);
        p0 += __shfl_xor_sync(0xffffffffu, p0, 2);
        p1 += __shfl_xor_sync(0xffffffffu, p1, 1);
        p1 += __shfl_xor_sync(0xffffffffu, p1, 2);
        int r0 = wr * 16 + g;
        if (wc == 0 && t4 == 0) { s_p[r0] = p0; s_p[r0 + 8] = p1; }
        __syncthreads();
        if (wc == 1 && t4 == 0) {
            if (row0 < n) g_t[row0] = p0 + s_p[r0];
            if (row1 < n) g_t[row1] = p1 + s_p[r0 + 8];
        }
    }
}

// ---------------- Fused layer 0: CIN=13 (FFMA path) ----------------
__global__ void __launch_bounds__(256) fused13(
    const float* __restrict__ x,
    const float* __restrict__ Wl, const float* __restrict__ bl,
    const float* __restrict__ Wr, int n)
{
    constexpr int ROWS = 32;
    constexpr int L = 28;
    __shared__ __align__(16) float w_s[2 * 13 * 64];
    __shared__ __align__(16) float in_s[ROWS * L];
    __shared__ float bl_s[64];

    float* hout = g_h[0];
    int tid = threadIdx.x;
    int base = blockIdx.x * ROWS;
    int warp = tid >> 5;
    int lane = tid & 31;

    for (int i = tid; i < 2 * 13 * 64; i += 256) w_s[i] = (i < 13 * 64) ? Wl[i] : Wr[i - 13 * 64];
    if (tid < 64) bl_s[tid] = bl[tid];

    for (int q = 0; q < 4; q++) {
        int r = warp * 4 + q;
        int row = base + r;
        float acc = 0.f;
        if (row < n) {
            int start = g_rowptr[row];
            int end = g_rowptr[row + 1];
            for (int j = start; j < end; j += 32) {
                int m = min(32, end - j);
                int eid = (lane < m) ? g_csr_src[j + lane] : 0;
#pragma unroll
                for (int k = 0; k < 32; k += 8) {
                    if (k >= m) break;
                    float v[8];
#pragma unroll
                    for (int u = 0; u < 8; u++) {
                        int s = __shfl_sync(0xffffffffu, eid, k + u);
                        v[u] = (lane < 13 && k + u < m) ? __ldg(&x[(size_t)s * 13 + lane]) : 0.f;
                    }
#pragma unroll
                    for (int u = 0; u < 8; u++) acc += v[u];
                }
            }
            float inv = 1.0f / (float)max(end - start, 1);
            if (lane < 13) {
                in_s[r * L + lane] = acc * inv;
                in_s[r * L + 14 + lane] = __ldg(&x[(size_t)row * 13 + lane]);
            }
        } else if (lane < 13) {
            in_s[r * L + lane] = 0.f;
            in_s[r * L + 14 + lane] = 0.f;
        }
    }
    __syncthreads();

    int rr = tid >> 4;
    int cg = tid & 15;
    int j0 = cg * 4;
    const float4* w4 = (const float4*)w_s;

    float a0[4], a1[4];
#pragma unroll
    for (int c = 0; c < 4; c++) { a0[c] = bl_s[j0 + c]; a1[c] = bl_s[j0 + c]; }

    const float* r0p = &in_s[rr * L];
    const float* r1p = &in_s[(rr + 16) * L];
#pragma unroll
    for (int k = 0; k < 13; k++) {
        float4 w = w4[k * 16 + cg];
        float x0 = r0p[k], x1 = r1p[k];
        a0[0] += x0 * w.x; a0[1] += x0 * w.y; a0[2] += x0 * w.z; a0[3] += x0 * w.w;
        a1[0] += x1 * w.x; a1[1] += x1 * w.y; a1[2] += x1 * w.z; a1[3] += x1 * w.w;
    }
#pragma unroll
    for (int k = 0; k < 13; k++) {
        float4 w = w4[(13 + k) * 16 + cg];
        float x0 = r0p[14 + k], x1 = r1p[14 + k];
        a0[0] += x0 * w.x; a0[1] += x0 * w.y; a0[2] += x0 * w.z; a0[3] += x0 * w.w;
        a1[0] += x1 * w.x; a1[1] += x1 * w.y; a1[2] += x1 * w.z; a1[3] += x1 * w.w;
    }

    int row0 = base + rr;
    int row1 = base + rr + 16;
    if (row0 < n) {
#pragma unroll
        for (int c = 0; c < 4; c++) a0[c] = fmaxf(a0[c], 0.f);
        *(float4*)(hout + (size_t)row0 * 64 + j0) = make_float4(a0[0], a0[1], a0[2], a0[3]);
    }
    if (row1 < n) {
#pragma unroll
        for (int c = 0; c < 4; c++) a1[c] = fmaxf(a1[c], 0.f);
        *(float4*)(hout + (size_t)row1 * 64 + j0) = make_float4(a1[0], a1[1], a1[2], a1[3]);
    }
}

// ---------------- Final layer (64 -> 1) ----------------
__global__ void __launch_bounds__(256) final_kernel(
    int in_idx,
    const float* __restrict__ Wr,
    const float* __restrict__ bl,
    float* __restrict__ out, int n)
{
    __shared__ float w[64];
    if (threadIdx.x < 64) w[threadIdx.x] = Wr[threadIdx.x];
    __syncthreads();
    const float* h = g_h[in_idx];

    int gw = (blockIdx.x * blockDim.x + threadIdx.x) >> 5;
    if (gw >= n) return;
    int lane = threadIdx.x & 31;

    int start = g_rowptr[gw];
    int end = g_rowptr[gw + 1];
    float sum = 0.f;
    for (int j = start + lane; j < end; j += 32) sum += __ldg(&g_t[g_csr_src[j]]);

    float inv = 1.0f / (float)max(end - start, 1);
    float2 hv = *(const float2*)(h + (size_t)gw * 64 + 2 * lane);
    float2 wv = *(const float2*)&w[2 * lane];
    float v = sum * inv + hv.x * wv.x + hv.y * wv.y;
#pragma unroll
    for (int off = 16; off >= 1; off >>= 1) v += __shfl_xor_sync(0xffffffffu, v, off);

    if (lane == 0) {
        float z = v + bl[0];
        out[gw] = 1.0f / (1.0f + __expf(-z));
    }
}

// ---------------- launch ----------------
extern "C" void kernel_launch(void* const* d_in, const int* in_sizes, int n_in,
                              void* d_out, int out_size) {
    const float* x = (const float*)d_in[0];
    const void* ei = d_in[1];
    const float* Wl[5]; const float* bl[5]; const float* Wr[5];
    for (int i = 0; i < 5; i++) {
        Wl[i] = (const float*)d_in[2 + 3 * i];
        bl[i] = (const float*)d_in[3 + 3 * i];
        Wr[i] = (const float*)d_in[4 + 3 * i];
    }
    int n = in_sizes[0] / 13;
    int E = in_sizes[1] / 2;
    float* out = (float*)d_out;

    int eb = (E + 255) / 256;
    int nb = (n + 255) / 256;
    int fb13 = (n + 31) / 32;
    int fbtc = (n + TC_ROWS - 1) / TC_ROWS;

    cudaFuncSetAttribute(fused64tc<false>, cudaFuncAttributeMaxDynamicSharedMemorySize, TC_DSMEM);
    cudaFuncSetAttribute(fused64tc<true>,  cudaFuncAttributeMaxDynamicSharedMemorySize, TC_DSMEM);

    zero_start<<<64, 256>>>((const int*)ei, E, n);
    count_kernel<<<eb, 256>>>(ei, E, n);
    scan_partial<<<nb, 256>>>(n);
    scan_bsum<<<1, 256>>>(nb, n);
    scan_final<<<nb, 256>>>(n);
    fill_kernel<<<eb, 256>>>(ei, E, n);

    fused13<<<fb13, 256>>>(x, Wl[0], bl[0], Wr[0], n);                                   // -> g_h[0]
    fused64tc<false><<<fbtc, 256, TC_DSMEM>>>(0, 1, Wl[1], bl[1], Wr[1], Wl[1], n);      // h0 -> h1
    fused64tc<false><<<fbtc, 256, TC_DSMEM>>>(1, 0, Wl[2], bl[2], Wr[2], Wl[2], n);      // h1 -> h0
    fused64tc<true><<<fbtc, 256, TC_DSMEM>>>(0, 1, Wl[3], bl[3], Wr[3], Wl[4], n);       // h0 -> h1, t = h3 @ Wl4
    final_kernel<<<(n * 32 + 255) / 256, 256>>>(1, Wr[4], bl[4], out, n);
}

// round 13
// speedup vs baseline: 1.0907x; 1.0114x over previous
#include <cuda_runtime.h>
#include <cstdint>

#define NMAX 50000
#define EMAX 800000

// Scratch (device globals; no allocation allowed)
__device__ __align__(256) float g_h[2][(size_t)NMAX * 64];
__device__ __align__(256) float g_agg[(size_t)NMAX * 64];
__device__ __align__(256) int   g_cnt[NMAX];
__device__ __align__(256) int   g_fill[NMAX];
__device__ __align__(256) int   g_rowptr[NMAX + 1];
__device__ __align__(256) int   g_csr_src[EMAX];
__device__ __align__(256) float g_t[NMAX];
__device__ __align__(256) int   g_bsum[256];
__device__ __align__(256) int   g_bscan[256];
__device__ int g_is64;

// ---------------- mma.sync tf32 helpers (compute_100-safe, sm_80+) ----------------
__device__ __forceinline__ uint32_t f2tf32(float x) {
    uint32_t r;
    asm("cvt.rna.tf32.f32 %0, %1;" : "=r"(r) : "f"(x));
    return r;
}
__device__ __forceinline__ void mma_tf32(float& d0, float& d1, float& d2, float& d3,
                                         uint32_t a0, uint32_t a1, uint32_t a2, uint32_t a3,
                                         uint32_t b0, uint32_t b1) {
    asm volatile(
        "mma.sync.aligned.m16n8k8.row.col.f32.tf32.tf32.f32 "
        "{%0,%1,%2,%3}, {%4,%5,%6,%7}, {%8,%9}, {%0,%1,%2,%3};"
        : "+f"(d0), "+f"(d1), "+f"(d2), "+f"(d3)
        : "r"(a0), "r"(a1), "r"(a2), "r"(a3), "r"(b0), "r"(b1));
}

// ---------------- zero + edge dtype detection (fused) ----------------
__global__ void zero_start(const int* ei32, int E, int n) {
    int i = blockIdx.x * blockDim.x + threadIdx.x;
    int stride = gridDim.x * blockDim.x;
    for (int j = i; j < n; j += stride) { g_cnt[j] = 0; g_fill[j] = 0; }
    if (i == 0) {
        int all0 = 1;
        for (int k = 0; k < 64; k++) {
            long long p = 1 + 2 * ((long long)k * (E / 2 - 1) / 64);
            if (ei32[p] != 0) { all0 = 0; break; }
        }
        g_is64 = all0;
    }
}

__device__ __forceinline__ int load_idx(const void* ei, int E, int half, int e, int is64, int n) {
    int v;
    if (is64) v = (int)((const long long*)ei)[(size_t)half * E + e];
    else      v = ((const int*)ei)[(size_t)half * E + e];
    return min(max(v, 0), n - 1);
}

__global__ void count_kernel(const void* __restrict__ ei, int E, int n) {
    int e = blockIdx.x * blockDim.x + threadIdx.x;
    if (e >= E) return;
    int d = load_idx(ei, E, 1, e, g_is64, n);
    atomicAdd(&g_cnt[d], 1);
}

// ---------------- 3-phase parallel exclusive scan ----------------
__global__ void __launch_bounds__(256) scan_partial(int n) {
    int t = threadIdx.x;
    int i = blockIdx.x * 256 + t;
    int v = (i < n) ? g_cnt[i] : 0;
    int w = v;
#pragma unroll
    for (int off = 16; off >= 1; off >>= 1) w += __shfl_xor_sync(0xffffffffu, w, off);
    __shared__ int red[8];
    if ((t & 31) == 0) red[t >> 5] = w;
    __syncthreads();
    if (t == 0) {
        int s = 0;
#pragma unroll
        for (int k = 0; k < 8; k++) s += red[k];
        g_bsum[blockIdx.x] = s;
    }
}

__global__ void __launch_bounds__(256) scan_bsum(int nb, int n) {
    __shared__ int s[256];
    int t = threadIdx.x;
    int v = (t < nb) ? g_bsum[t] : 0;
    s[t] = v;
    __syncthreads();
#pragma unroll
    for (int off = 1; off < 256; off <<= 1) {
        int a = s[t];
        int b = (t >= off) ? s[t - off] : 0;
        __syncthreads();
        s[t] = a + b;
        __syncthreads();
    }
    if (t < nb) g_bscan[t] = s[t] - v;
    if (t == nb - 1) g_rowptr[n] = s[t];
}

__global__ void __launch_bounds__(256) scan_final(int n) {
    int t = threadIdx.x;
    int lane = t & 31;
    int wid = t >> 5;
    int i = blockIdx.x * 256 + t;
    int v = (i < n) ? g_cnt[i] : 0;
    int inc = v;
#pragma unroll
    for (int off = 1; off < 32; off <<= 1) {
        int u = __shfl_up_sync(0xffffffffu, inc, off);
        if (lane >= off) inc += u;
    }
    __shared__ int wsum[8];
    if (lane == 31) wsum[wid] = inc;
    __syncthreads();
    if (t == 0) {
        int s = 0;
#pragma unroll
        for (int k = 0; k < 8; k++) { int u = wsum[k]; wsum[k] = s; s += u; }
    }
    __syncthreads();
    if (i < n) g_rowptr[i] = g_bscan[blockIdx.x] + wsum[wid] + inc - v;
}

__global__ void fill_kernel(const void* __restrict__ ei, int E, int n) {
    int e = blockIdx.x * blockDim.x + threadIdx.x;
    if (e >= E) return;
    int is64 = g_is64;
    int s = load_idx(ei, E, 0, e, is64, n);
    int d = load_idx(ei, E, 1, e, is64, n);
    int pos = g_rowptr[d] + atomicAdd(&g_fill[d], 1);
    if (pos < EMAX) g_csr_src[pos] = s;
}

// ---------------- Standalone gather: warp per node, zero smem, high occupancy ----------
// 16-lane float4 edge reads (2 edges per warp-LDG, 8 in flight). Writes mean-agg to g_agg.
__global__ void __launch_bounds__(256, 4) gather64(int in_idx, int n) {
    const float* hin = g_h[in_idx];
    int gw = (blockIdx.x * blockDim.x + threadIdx.x) >> 5;
    if (gw >= n) return;
    int lane = threadIdx.x & 31;
    int lane16 = lane & 15;
    int half = lane >> 4;

    int start = g_rowptr[gw];
    int end = g_rowptr[gw + 1];
    float4 acc = make_float4(0.f, 0.f, 0.f, 0.f);
    for (int j = start; j < end; j += 32) {
        int m = min(32, end - j);
        int eid = (lane < m) ? g_csr_src[j + lane] : 0;
#pragma unroll
        for (int k = 0; k < 32; k += 16) {
            if (k >= m) break;
            float4 v[8];
#pragma unroll
            for (int u = 0; u < 8; u++) {
                int idx = k + 2 * u + half;
                int s = __shfl_sync(0xffffffffu, eid, idx);
                if (idx < m)
                    v[u] = *(const float4*)(hin + (size_t)s * 64 + lane16 * 4);
                else
                    v[u] = make_float4(0.f, 0.f, 0.f, 0.f);
            }
#pragma unroll
            for (int u = 0; u < 8; u++) {
                acc.x += v[u].x; acc.y += v[u].y; acc.z += v[u].z; acc.w += v[u].w;
            }
        }
    }
    acc.x += __shfl_xor_sync(0xffffffffu, acc.x, 16);
    acc.y += __shfl_xor_sync(0xffffffffu, acc.y, 16);
    acc.z += __shfl_xor_sync(0xffffffffu, acc.z, 16);
    acc.w += __shfl_xor_sync(0xffffffffu, acc.w, 16);
    float inv = 1.0f / (float)max(end - start, 1);
    acc.x *= inv; acc.y *= inv; acc.z *= inv; acc.w *= inv;
    if (half == 0)
        *(float4*)&g_agg[(size_t)gw * 64 + lane16 * 4] = acc;
}

// ---------------- Layer GEMM: load agg+h -> smem, tf32 mma (3xTF32) ----------------
// Block 256 thr (8 warps), M=64 rows/block.
// A[64x128] = [agg|h] fp32 in smem (stride 132). B[64x128] = [Wl;Wr]^T fp32 (stride 132).
// GEMM: warp (wr=warp&3, wc=warp>>2) -> rows wr*16..+16, cols wc*32..+32.
#define TC_ROWS 64
#define TC_LA 132
#define TC_DSMEM (2 * 64 * TC_LA * 4)

template <bool FT>
__global__ void __launch_bounds__(256, 3) fused64tc(
    int in_idx, int out_idx,
    const float* __restrict__ Wl, const float* __restrict__ bl,
    const float* __restrict__ Wr, const float* __restrict__ Wl4,
    int n)
{
    extern __shared__ __align__(16) float dyn[];
    float* a_s = dyn;                 // 64 x 132
    float* b_s = a_s + 64 * TC_LA;    // 64 x 132 (n-major: b_s[nn][kk])
    __shared__ float bl_s[64];
    __shared__ float wl4_s[64];
    __shared__ float s_p[64];

    const float* hin = g_h[in_idx];
    float* hout = g_h[out_idx];

    int tid = threadIdx.x;
    int base = blockIdx.x * TC_ROWS;
    int warp = tid >> 5;
    int lane = tid & 31;

    // B tile: b_s[nn][kk] = (kk<64 ? Wl[kk][nn] : Wr[kk-64][nn])
    for (int i = tid; i < 64 * 128; i += 256) {
        int nn = i & 63;
        int kk = i >> 6;
        float v = (kk < 64) ? Wl[kk * 64 + nn] : Wr[(kk - 64) * 64 + nn];
        b_s[nn * TC_LA + kk] = v;
    }
    if (tid < 64) {
        bl_s[tid] = bl[tid];
        if (FT) wl4_s[tid] = Wl4[tid];
    }

    // Phase 1: coalesced load of agg + h into a_s (16 float4 per row each side)
    for (int i = tid; i < 64 * 16; i += 256) {
        int r = i >> 4;
        int c4 = i & 15;
        int row = base + r;
        float4 av = make_float4(0.f, 0.f, 0.f, 0.f);
        float4 hv = make_float4(0.f, 0.f, 0.f, 0.f);
        if (row < n) {
            av = *(const float4*)&g_agg[(size_t)row * 64 + c4 * 4];
            hv = *(const float4*)(hin + (size_t)row * 64 + c4 * 4);
        }
        *(float4*)&a_s[r * TC_LA + c4 * 4] = av;
        *(float4*)&a_s[r * TC_LA + 64 + c4 * 4] = hv;
    }
    __syncthreads();

    // Phase 2: tensor-core GEMM (3xTF32 error compensation).
    int wr = warp & 3;
    int wc = warp >> 2;
    int g = lane >> 2;       // 0..7
    int t4 = lane & 3;       // 0..3
    int ar0 = wr * 16 + g;   // fragment rows ar0, ar0+8

    float d[4][4];
#pragma unroll
    for (int nt = 0; nt < 4; nt++)
#pragma unroll
        for (int c = 0; c < 4; c++) d[nt][c] = 0.f;

#pragma unroll
    for (int ks = 0; ks < 16; ks++) {
        int k0 = ks * 8;
        float af[4];
        af[0] = a_s[ar0 * TC_LA + k0 + t4];
        af[1] = a_s[(ar0 + 8) * TC_LA + k0 + t4];
        af[2] = a_s[ar0 * TC_LA + k0 + t4 + 4];
        af[3] = a_s[(ar0 + 8) * TC_LA + k0 + t4 + 4];
        uint32_t ah[4], al[4];
#pragma unroll
        for (int i = 0; i < 4; i++) {
            ah[i] = f2tf32(af[i]);
            al[i] = f2tf32(af[i] - __uint_as_float(ah[i]));
        }
#pragma unroll
        for (int nt = 0; nt < 4; nt++) {
            int nn = wc * 32 + nt * 8 + g;
            float bf0 = b_s[nn * TC_LA + k0 + t4];
            float bf1 = b_s[nn * TC_LA + k0 + t4 + 4];
            uint32_t bh0 = f2tf32(bf0), bh1 = f2tf32(bf1);
            uint32_t bl0 = f2tf32(bf0 - __uint_as_float(bh0));
            uint32_t bl1 = f2tf32(bf1 - __uint_as_float(bh1));
            mma_tf32(d[nt][0], d[nt][1], d[nt][2], d[nt][3], ah[0], ah[1], ah[2], ah[3], bh0, bh1);
            mma_tf32(d[nt][0], d[nt][1], d[nt][2], d[nt][3], al[0], al[1], al[2], al[3], bh0, bh1);
            mma_tf32(d[nt][0], d[nt][1], d[nt][2], d[nt][3], ah[0], ah[1], ah[2], ah[3], bl0, bl1);
        }
    }

    // Epilogue: bias + relu + store.
    int row0 = base + wr * 16 + g;
    int row1 = row0 + 8;
    float p0 = 0.f, p1 = 0.f;
#pragma unroll
    for (int nt = 0; nt < 4; nt++) {
        int c = wc * 32 + nt * 8 + 2 * t4;
        float v0 = fmaxf(d[nt][0] + bl_s[c], 0.f);
        float v1 = fmaxf(d[nt][1] + bl_s[c + 1], 0.f);
        float v2 = fmaxf(d[nt][2] + bl_s[c], 0.f);
        float v3 = fmaxf(d[nt][3] + bl_s[c + 1], 0.f);
        if (row0 < n) *(float2*)(hout + (size_t)row0 * 64 + c) = make_float2(v0, v1);
        if (row1 < n) *(float2*)(hout + (size_t)row1 * 64 + c) = make_float2(v2, v3);
        if (FT) {
            p0 += v0 * wl4_s[c] + v1 * wl4_s[c + 1];
            p1 += v2 * wl4_s[c] + v3 * wl4_s[c + 1];
        }
    }

    if (FT) {
        p0 += __shfl_xor_sync(0xffffffffu, p0, 1);
        p0 += __shfl_xor_sync(0xffffffffu, p0, 2);
        p1 += __shfl_xor_sync(0xffffffffu, p1, 1);
        p1 += __shfl_xor_sync(0xffffffffu, p1, 2);
        int r0 = wr * 16 + g;
        if (wc == 0 && t4 == 0) { s_p[r0] = p0; s_p[r0 + 8] = p1; }
        __syncthreads();
        if (wc == 1 && t4 == 0) {
            if (row0 < n) g_t[row0] = p0 + s_p[r0];
            if (row1 < n) g_t[row1] = p1 + s_p[r0 + 8];
        }
    }
}

// ---------------- Fused layer 0: CIN=13 (FFMA path) ----------------
__global__ void __launch_bounds__(256) fused13(
    const float* __restrict__ x,
    const float* __restrict__ Wl, const float* __restrict__ bl,
    const float* __restrict__ Wr, int n)
{
    constexpr int ROWS = 32;
    constexpr int L = 28;
    __shared__ __align__(16) float w_s[2 * 13 * 64];
    __shared__ __align__(16) float in_s[ROWS * L];
    __shared__ float bl_s[64];

    float* hout = g_h[0];
    int tid = threadIdx.x;
    int base = blockIdx.x * ROWS;
    int warp = tid >> 5;
    int lane = tid & 31;

    for (int i = tid; i < 2 * 13 * 64; i += 256) w_s[i] = (i < 13 * 64) ? Wl[i] : Wr[i - 13 * 64];
    if (tid < 64) bl_s[tid] = bl[tid];

    for (int q = 0; q < 4; q++) {
        int r = warp * 4 + q;
        int row = base + r;
        float acc = 0.f;
        if (row < n) {
            int start = g_rowptr[row];
            int end = g_rowptr[row + 1];
            for (int j = start; j < end; j += 32) {
                int m = min(32, end - j);
                int eid = (lane < m) ? g_csr_src[j + lane] : 0;
#pragma unroll
                for (int k = 0; k < 32; k += 8) {
                    if (k >= m) break;
                    float v[8];
#pragma unroll
                    for (int u = 0; u < 8; u++) {
                        int s = __shfl_sync(0xffffffffu, eid, k + u);
                        v[u] = (lane < 13 && k + u < m) ? __ldg(&x[(size_t)s * 13 + lane]) : 0.f;
                    }
#pragma unroll
                    for (int u = 0; u < 8; u++) acc += v[u];
                }
            }
            float inv = 1.0f / (float)max(end - start, 1);
            if (lane < 13) {
                in_s[r * L + lane] = acc * inv;
                in_s[r * L + 14 + lane] = __ldg(&x[(size_t)row * 13 + lane]);
            }
        } else if (lane < 13) {
            in_s[r * L + lane] = 0.f;
            in_s[r * L + 14 + lane] = 0.f;
        }
    }
    __syncthreads();

    int rr = tid >> 4;
    int cg = tid & 15;
    int j0 = cg * 4;
    const float4* w4 = (const float4*)w_s;

    float a0[4], a1[4];
#pragma unroll
    for (int c = 0; c < 4; c++) { a0[c] = bl_s[j0 + c]; a1[c] = bl_s[j0 + c]; }

    const float* r0p = &in_s[rr * L];
    const float* r1p = &in_s[(rr + 16) * L];
#pragma unroll
    for (int k = 0; k < 13; k++) {
        float4 w = w4[k * 16 + cg];
        float x0 = r0p[k], x1 = r1p[k];
        a0[0] += x0 * w.x; a0[1] += x0 * w.y; a0[2] += x0 * w.z; a0[3] += x0 * w.w;
        a1[0] += x1 * w.x; a1[1] += x1 * w.y; a1[2] += x1 * w.z; a1[3] += x1 * w.w;
    }
#pragma unroll
    for (int k = 0; k < 13; k++) {
        float4 w = w4[(13 + k) * 16 + cg];
        float x0 = r0p[14 + k], x1 = r1p[14 + k];
        a0[0] += x0 * w.x; a0[1] += x0 * w.y; a0[2] += x0 * w.z; a0[3] += x0 * w.w;
        a1[0] += x1 * w.x; a1[1] += x1 * w.y; a1[2] += x1 * w.z; a1[3] += x1 * w.w;
    }

    int row0 = base + rr;
    int row1 = base + rr + 16;
    if (row0 < n) {
#pragma unroll
        for (int c = 0; c < 4; c++) a0[c] = fmaxf(a0[c], 0.f);
        *(float4*)(hout + (size_t)row0 * 64 + j0) = make_float4(a0[0], a0[1], a0[2], a0[3]);
    }
    if (row1 < n) {
#pragma unroll
        for (int c = 0; c < 4; c++) a1[c] = fmaxf(a1[c], 0.f);
        *(float4*)(hout + (size_t)row1 * 64 + j0) = make_float4(a1[0], a1[1], a1[2], a1[3]);
    }
}

// ---------------- Final layer (64 -> 1) ----------------
__global__ void __launch_bounds__(256) final_kernel(
    int in_idx,
    const float* __restrict__ Wr,
    const float* __restrict__ bl,
    float* __restrict__ out, int n)
{
    __shared__ float w[64];
    if (threadIdx.x < 64) w[threadIdx.x] = Wr[threadIdx.x];
    __syncthreads();
    const float* h = g_h[in_idx];

    int gw = (blockIdx.x * blockDim.x + threadIdx.x) >> 5;
    if (gw >= n) return;
    int lane = threadIdx.x & 31;

    int start = g_rowptr[gw];
    int end = g_rowptr[gw + 1];
    float sum = 0.f;
    for (int j = start + lane; j < end; j += 32) sum += __ldg(&g_t[g_csr_src[j]]);

    float inv = 1.0f / (float)max(end - start, 1);
    float2 hv = *(const float2*)(h + (size_t)gw * 64 + 2 * lane);
    float2 wv = *(const float2*)&w[2 * lane];
    float v = sum * inv + hv.x * wv.x + hv.y * wv.y;
#pragma unroll
    for (int off = 16; off >= 1; off >>= 1) v += __shfl_xor_sync(0xffffffffu, v, off);

    if (lane == 0) {
        float z = v + bl[0];
        out[gw] = 1.0f / (1.0f + __expf(-z));
    }
}

// ---------------- launch ----------------
extern "C" void kernel_launch(void* const* d_in, const int* in_sizes, int n_in,
                              void* d_out, int out_size) {
    const float* x = (const float*)d_in[0];
    const void* ei = d_in[1];
    const float* Wl[5]; const float* bl[5]; const float* Wr[5];
    for (int i = 0; i < 5; i++) {
        Wl[i] = (const float*)d_in[2 + 3 * i];
        bl[i] = (const float*)d_in[3 + 3 * i];
        Wr[i] = (const float*)d_in[4 + 3 * i];
    }
    int n = in_sizes[0] / 13;
    int E = in_sizes[1] / 2;
    float* out = (float*)d_out;

    int eb = (E + 255) / 256;
    int nb = (n + 255) / 256;
    int fb13 = (n + 31) / 32;
    int fbtc = (n + TC_ROWS - 1) / TC_ROWS;
    int gb = (n * 32 + 255) / 256;

    cudaFuncSetAttribute(fused64tc<false>, cudaFuncAttributeMaxDynamicSharedMemorySize, TC_DSMEM);
    cudaFuncSetAttribute(fused64tc<true>,  cudaFuncAttributeMaxDynamicSharedMemorySize, TC_DSMEM);

    zero_start<<<64, 256>>>((const int*)ei, E, n);
    count_kernel<<<eb, 256>>>(ei, E, n);
    scan_partial<<<nb, 256>>>(n);
    scan_bsum<<<1, 256>>>(nb, n);
    scan_final<<<nb, 256>>>(n);
    fill_kernel<<<eb, 256>>>(ei, E, n);

    fused13<<<fb13, 256>>>(x, Wl[0], bl[0], Wr[0], n);                                   // -> g_h[0]

    gather64<<<gb, 256>>>(0, n);
    fused64tc<false><<<fbtc, 256, TC_DSMEM>>>(0, 1, Wl[1], bl[1], Wr[1], Wl[1], n);      // h0 -> h1
    gather64<<<gb, 256>>>(1, n);
    fused64tc<false><<<fbtc, 256, TC_DSMEM>>>(1, 0, Wl[2], bl[2], Wr[2], Wl[2], n);      // h1 -> h0
    gather64<<<gb, 256>>>(0, n);
    fused64tc<true><<<fbtc, 256, TC_DSMEM>>>(0, 1, Wl[3], bl[3], Wr[3], Wl[4], n);       // h0 -> h1, t = h3 @ Wl4

    final_kernel<<<(n * 32 + 255) / 256, 256>>>(1, Wr[4], bl[4], out, n);
}

// round 14
// speedup vs baseline: 1.1746x; 1.0769x over previous
#include <cuda_runtime.h>
#include <cstdint>

#define NMAX 50000
#define EMAX 800000

// Scratch (device globals; no allocation allowed). Zero-initialized at load;
// every kernel_launch call leaves g_cnt zeroed (self-restoring invariant).
__device__ __align__(256) float g_h[2][(size_t)NMAX * 64];
__device__ __align__(256) float g_agg[(size_t)NMAX * 64];
__device__ __align__(256) int   g_cnt[NMAX];
__device__ __align__(256) int   g_fill[NMAX];
__device__ __align__(256) int   g_rowptr[NMAX + 1];
__device__ __align__(256) int   g_csr_src[EMAX];
__device__ __align__(256) float g_t[NMAX];
__device__ __align__(256) int   g_bsum[256];
__device__ __align__(256) int   g_bscan[256];
__device__ int g_is64;

// ---------------- mma.sync tf32 helpers (compute_100-safe, sm_80+) ----------------
__device__ __forceinline__ uint32_t f2tf32(float x) {
    uint32_t r;
    asm("cvt.rna.tf32.f32 %0, %1;" : "=r"(r) : "f"(x));
    return r;
}
__device__ __forceinline__ void mma_tf32(float& d0, float& d1, float& d2, float& d3,
                                         uint32_t a0, uint32_t a1, uint32_t a2, uint32_t a3,
                                         uint32_t b0, uint32_t b1) {
    asm volatile(
        "mma.sync.aligned.m16n8k8.row.col.f32.tf32.tf32.f32 "
        "{%0,%1,%2,%3}, {%4,%5,%6,%7}, {%8,%9}, {%0,%1,%2,%3};"
        : "+f"(d0), "+f"(d1), "+f"(d2), "+f"(d3)
        : "r"(a0), "r"(a1), "r"(a2), "r"(a3), "r"(b0), "r"(b1));
}

// ---------------- edge dtype detection ----------------
__global__ void detect_kernel(const int* ei32, int E) {
    int all0 = 1;
    for (int k = 0; k < 64; k++) {
        long long p = 1 + 2 * ((long long)k * (E / 2 - 1) / 64);
        if (ei32[p] != 0) { all0 = 0; break; }
    }
    g_is64 = all0;
}

__device__ __forceinline__ int load_idx(const void* ei, int E, int half, int e, int is64, int n) {
    int v;
    if (is64) v = (int)((const long long*)ei)[(size_t)half * E + e];
    else      v = ((const int*)ei)[(size_t)half * E + e];
    return min(max(v, 0), n - 1);
}

// count relies on g_cnt == 0 at entry (zero-init at load; re-zeroed by scan_final)
__global__ void count_kernel(const void* __restrict__ ei, int E, int n) {
    int e = blockIdx.x * blockDim.x + threadIdx.x;
    if (e >= E) return;
    int d = load_idx(ei, E, 1, e, g_is64, n);
    atomicAdd(&g_cnt[d], 1);
}

// ---------------- 3-phase parallel exclusive scan ----------------
__global__ void __launch_bounds__(256) scan_partial(int n) {
    int t = threadIdx.x;
    int i = blockIdx.x * 256 + t;
    int v = (i < n) ? g_cnt[i] : 0;
    int w = v;
#pragma unroll
    for (int off = 16; off >= 1; off >>= 1) w += __shfl_xor_sync(0xffffffffu, w, off);
    __shared__ int red[8];
    if ((t & 31) == 0) red[t >> 5] = w;
    __syncthreads();
    if (t == 0) {
        int s = 0;
#pragma unroll
        for (int k = 0; k < 8; k++) s += red[k];
        g_bsum[blockIdx.x] = s;
    }
}

__global__ void __launch_bounds__(256) scan_bsum(int nb, int n) {
    __shared__ int s[256];
    int t = threadIdx.x;
    int v = (t < nb) ? g_bsum[t] : 0;
    s[t] = v;
    __syncthreads();
#pragma unroll
    for (int off = 1; off < 256; off <<= 1) {
        int a = s[t];
        int b = (t >= off) ? s[t - off] : 0;
        __syncthreads();
        s[t] = a + b;
        __syncthreads();
    }
    if (t < nb) g_bscan[t] = s[t] - v;
    if (t == nb - 1) g_rowptr[n] = s[t];
}

// writes rowptr, seeds g_fill = rowptr start, and re-zeroes g_cnt (self-restoring)
__global__ void __launch_bounds__(256) scan_final(int n) {
    int t = threadIdx.x;
    int lane = t & 31;
    int wid = t >> 5;
    int i = blockIdx.x * 256 + t;
    int v = (i < n) ? g_cnt[i] : 0;
    int inc = v;
#pragma unroll
    for (int off = 1; off < 32; off <<= 1) {
        int u = __shfl_up_sync(0xffffffffu, inc, off);
        if (lane >= off) inc += u;
    }
    __shared__ int wsum[8];
    if (lane == 31) wsum[wid] = inc;
    __syncthreads();
    if (t == 0) {
        int s = 0;
#pragma unroll
        for (int k = 0; k < 8; k++) { int u = wsum[k]; wsum[k] = s; s += u; }
    }
    __syncthreads();
    if (i < n) {
        int start = g_bscan[blockIdx.x] + wsum[wid] + inc - v;
        g_rowptr[i] = start;
        g_fill[i] = start;
        g_cnt[i] = 0;
    }
}

__global__ void fill_kernel(const void* __restrict__ ei, int E, int n) {
    int e = blockIdx.x * blockDim.x + threadIdx.x;
    if (e >= E) return;
    int is64 = g_is64;
    int s = load_idx(ei, E, 0, e, is64, n);
    int d = load_idx(ei, E, 1, e, is64, n);
    int pos = atomicAdd(&g_fill[d], 1);
    if (pos < EMAX) g_csr_src[pos] = s;
}

// ---------------- Gather: TWO nodes per warp (16 lanes each), zero smem -------------
// Each half-warp owns one node: 16 lanes x float4 = full 256B row per edge load,
// 8 loads in flight per half (16/warp). No cross-lane reduce: each lane accumulates
// its own 4 columns over all edges and writes its float4 directly.
__global__ void __launch_bounds__(256, 4) gather64(int in_idx, int n) {
    const float* hin = g_h[in_idx];
    int gwarp = (blockIdx.x * blockDim.x + threadIdx.x) >> 5;
    int lane = threadIdx.x & 31;
    int half = lane >> 4;
    int lane16 = lane & 15;
    uint32_t hmask = half ? 0xffff0000u : 0x0000ffffu;

    int node = gwarp * 2 + half;
    int start = 0, end = 0;
    if (node < n) { start = g_rowptr[node]; end = g_rowptr[node + 1]; }

    float4 acc = make_float4(0.f, 0.f, 0.f, 0.f);
    for (int j = start; j < end; j += 16) {
        int m = min(16, end - j);
        int eid = (lane16 < m) ? g_csr_src[j + lane16] : 0;
#pragma unroll
        for (int k = 0; k < 16; k += 8) {
            if (k >= m) break;
            float4 v[8];
#pragma unroll
            for (int u = 0; u < 8; u++) {
                int idx = k + u;
                int s = __shfl_sync(hmask, eid, idx, 16);
                if (idx < m)
                    v[u] = *(const float4*)(hin + (size_t)s * 64 + lane16 * 4);
                else
                    v[u] = make_float4(0.f, 0.f, 0.f, 0.f);
            }
#pragma unroll
            for (int u = 0; u < 8; u++) {
                acc.x += v[u].x; acc.y += v[u].y; acc.z += v[u].z; acc.w += v[u].w;
            }
        }
    }
    if (node < n) {
        float inv = 1.0f / (float)max(end - start, 1);
        acc.x *= inv; acc.y *= inv; acc.z *= inv; acc.w *= inv;
        *(float4*)&g_agg[(size_t)node * 64 + lane16 * 4] = acc;
    }
}

// ---------------- Layer GEMM: load agg+h -> smem, tf32 mma (3xTF32) ----------------
#define TC_ROWS 64
#define TC_LA 132
#define TC_DSMEM (2 * 64 * TC_LA * 4)

template <bool FT>
__global__ void __launch_bounds__(256, 3) fused64tc(
    int in_idx, int out_idx,
    const float* __restrict__ Wl, const float* __restrict__ bl,
    const float* __restrict__ Wr, const float* __restrict__ Wl4,
    int n)
{
    extern __shared__ __align__(16) float dyn[];
    float* a_s = dyn;                 // 64 x 132
    float* b_s = a_s + 64 * TC_LA;    // 64 x 132 (n-major: b_s[nn][kk])
    __shared__ float bl_s[64];
    __shared__ float wl4_s[64];
    __shared__ float s_p[64];

    const float* hin = g_h[in_idx];
    float* hout = g_h[out_idx];

    int tid = threadIdx.x;
    int base = blockIdx.x * TC_ROWS;
    int warp = tid >> 5;
    int lane = tid & 31;

    for (int i = tid; i < 64 * 128; i += 256) {
        int nn = i & 63;
        int kk = i >> 6;
        float v = (kk < 64) ? Wl[kk * 64 + nn] : Wr[(kk - 64) * 64 + nn];
        b_s[nn * TC_LA + kk] = v;
    }
    if (tid < 64) {
        bl_s[tid] = bl[tid];
        if (FT) wl4_s[tid] = Wl4[tid];
    }

    for (int i = tid; i < 64 * 16; i += 256) {
        int r = i >> 4;
        int c4 = i & 15;
        int row = base + r;
        float4 av = make_float4(0.f, 0.f, 0.f, 0.f);
        float4 hv = make_float4(0.f, 0.f, 0.f, 0.f);
        if (row < n) {
            av = *(const float4*)&g_agg[(size_t)row * 64 + c4 * 4];
            hv = *(const float4*)(hin + (size_t)row * 64 + c4 * 4);
        }
        *(float4*)&a_s[r * TC_LA + c4 * 4] = av;
        *(float4*)&a_s[r * TC_LA + 64 + c4 * 4] = hv;
    }
    __syncthreads();

    int wr = warp & 3;
    int wc = warp >> 2;
    int g = lane >> 2;
    int t4 = lane & 3;
    int ar0 = wr * 16 + g;

    float d[4][4];
#pragma unroll
    for (int nt = 0; nt < 4; nt++)
#pragma unroll
        for (int c = 0; c < 4; c++) d[nt][c] = 0.f;

#pragma unroll
    for (int ks = 0; ks < 16; ks++) {
        int k0 = ks * 8;
        float af[4];
        af[0] = a_s[ar0 * TC_LA + k0 + t4];
        af[1] = a_s[(ar0 + 8) * TC_LA + k0 + t4];
        af[2] = a_s[ar0 * TC_LA + k0 + t4 + 4];
        af[3] = a_s[(ar0 + 8) * TC_LA + k0 + t4 + 4];
        uint32_t ah[4], al[4];
#pragma unroll
        for (int i = 0; i < 4; i++) {
            ah[i] = f2tf32(af[i]);
            al[i] = f2tf32(af[i] - __uint_as_float(ah[i]));
        }
#pragma unroll
        for (int nt = 0; nt < 4; nt++) {
            int nn = wc * 32 + nt * 8 + g;
            float bf0 = b_s[nn * TC_LA + k0 + t4];
            float bf1 = b_s[nn * TC_LA + k0 + t4 + 4];
            uint32_t bh0 = f2tf32(bf0), bh1 = f2tf32(bf1);
            uint32_t bl0 = f2tf32(bf0 - __uint_as_float(bh0));
            uint32_t bl1 = f2tf32(bf1 - __uint_as_float(bh1));
            mma_tf32(d[nt][0], d[nt][1], d[nt][2], d[nt][3], ah[0], ah[1], ah[2], ah[3], bh0, bh1);
            mma_tf32(d[nt][0], d[nt][1], d[nt][2], d[nt][3], al[0], al[1], al[2], al[3], bh0, bh1);
            mma_tf32(d[nt][0], d[nt][1], d[nt][2], d[nt][3], ah[0], ah[1], ah[2], ah[3], bl0, bl1);
        }
    }

    int row0 = base + wr * 16 + g;
    int row1 = row0 + 8;
    float p0 = 0.f, p1 = 0.f;
#pragma unroll
    for (int nt = 0; nt < 4; nt++) {
        int c = wc * 32 + nt * 8 + 2 * t4;
        float v0 = fmaxf(d[nt][0] + bl_s[c], 0.f);
        float v1 = fmaxf(d[nt][1] + bl_s[c + 1], 0.f);
        float v2 = fmaxf(d[nt][2] + bl_s[c], 0.f);
        float v3 = fmaxf(d[nt][3] + bl_s[c + 1], 0.f);
        if (row0 < n) *(float2*)(hout + (size_t)row0 * 64 + c) = make_float2(v0, v1);
        if (row1 < n) *(float2*)(hout + (size_t)row1 * 64 + c) = make_float2(v2, v3);
        if (FT) {
            p0 += v0 * wl4_s[c] + v1 * wl4_s[c + 1];
            p1 += v2 * wl4_s[c] + v3 * wl4_s[c + 1];
        }
    }

    if (FT) {
        p0 += __shfl_xor_sync(0xffffffffu, p0, 1);
        p0 += __shfl_xor_sync(0xffffffffu, p0, 2);
        p1 += __shfl_xor_sync(0xffffffffu, p1, 1);
        p1 += __shfl_xor_sync(0xffffffffu, p1, 2);
        int r0 = wr * 16 + g;
        if (wc == 0 && t4 == 0) { s_p[r0] = p0; s_p[r0 + 8] = p1; }
        __syncthreads();
        if (wc == 1 && t4 == 0) {
            if (row0 < n) g_t[row0] = p0 + s_p[r0];
            if (row1 < n) g_t[row1] = p1 + s_p[r0 + 8];
        }
    }
}

// ---------------- Fused layer 0: CIN=13 (FFMA path) ----------------
__global__ void __launch_bounds__(256) fused13(
    const float* __restrict__ x,
    const float* __restrict__ Wl, const float* __restrict__ bl,
    const float* __restrict__ Wr, int n)
{
    constexpr int ROWS = 32;
    constexpr int L = 28;
    __shared__ __align__(16) float w_s[2 * 13 * 64];
    __shared__ __align__(16) float in_s[ROWS * L];
    __shared__ float bl_s[64];

    float* hout = g_h[0];
    int tid = threadIdx.x;
    int base = blockIdx.x * ROWS;
    int warp = tid >> 5;
    int lane = tid & 31;

    for (int i = tid; i < 2 * 13 * 64; i += 256) w_s[i] = (i < 13 * 64) ? Wl[i] : Wr[i - 13 * 64];
    if (tid < 64) bl_s[tid] = bl[tid];

    for (int q = 0; q < 4; q++) {
        int r = warp * 4 + q;
        int row = base + r;
        float acc = 0.f;
        if (row < n) {
            int start = g_rowptr[row];
            int end = g_rowptr[row + 1];
            for (int j = start; j < end; j += 32) {
                int m = min(32, end - j);
                int eid = (lane < m) ? g_csr_src[j + lane] : 0;
#pragma unroll
                for (int k = 0; k < 32; k += 8) {
                    if (k >= m) break;
                    float v[8];
#pragma unroll
                    for (int u = 0; u < 8; u++) {
                        int s = __shfl_sync(0xffffffffu, eid, k + u);
                        v[u] = (lane < 13 && k + u < m) ? __ldg(&x[(size_t)s * 13 + lane]) : 0.f;
                    }
#pragma unroll
                    for (int u = 0; u < 8; u++) acc += v[u];
                }
            }
            float inv = 1.0f / (float)max(end - start, 1);
            if (lane < 13) {
                in_s[r * L + lane] = acc * inv;
                in_s[r * L + 14 + lane] = __ldg(&x[(size_t)row * 13 + lane]);
            }
        } else if (lane < 13) {
            in_s[r * L + lane] = 0.f;
            in_s[r * L + 14 + lane] = 0.f;
        }
    }
    __syncthreads();

    int rr = tid >> 4;
    int cg = tid & 15;
    int j0 = cg * 4;
    const float4* w4 = (const float4*)w_s;

    float a0[4], a1[4];
#pragma unroll
    for (int c = 0; c < 4; c++) { a0[c] = bl_s[j0 + c]; a1[c] = bl_s[j0 + c]; }

    const float* r0p = &in_s[rr * L];
    const float* r1p = &in_s[(rr + 16) * L];
#pragma unroll
    for (int k = 0; k < 13; k++) {
        float4 w = w4[k * 16 + cg];
        float x0 = r0p[k], x1 = r1p[k];
        a0[0] += x0 * w.x; a0[1] += x0 * w.y; a0[2] += x0 * w.z; a0[3] += x0 * w.w;
        a1[0] += x1 * w.x; a1[1] += x1 * w.y; a1[2] += x1 * w.z; a1[3] += x1 * w.w;
    }
#pragma unroll
    for (int k = 0; k < 13; k++) {
        float4 w = w4[(13 + k) * 16 + cg];
        float x0 = r0p[14 + k], x1 = r1p[14 + k];
        a0[0] += x0 * w.x; a0[1] += x0 * w.y; a0[2] += x0 * w.z; a0[3] += x0 * w.w;
        a1[0] += x1 * w.x; a1[1] += x1 * w.y; a1[2] += x1 * w.z; a1[3] += x1 * w.w;
    }

    int row0 = base + rr;
    int row1 = base + rr + 16;
    if (row0 < n) {
#pragma unroll
        for (int c = 0; c < 4; c++) a0[c] = fmaxf(a0[c], 0.f);
        *(float4*)(hout + (size_t)row0 * 64 + j0) = make_float4(a0[0], a0[1], a0[2], a0[3]);
    }
    if (row1 < n) {
#pragma unroll
        for (int c = 0; c < 4; c++) a1[c] = fmaxf(a1[c], 0.f);
        *(float4*)(hout + (size_t)row1 * 64 + j0) = make_float4(a1[0], a1[1], a1[2], a1[3]);
    }
}

// ---------------- Final layer (64 -> 1) ----------------
__global__ void __launch_bounds__(256) final_kernel(
    int in_idx,
    const float* __restrict__ Wr,
    const float* __restrict__ bl,
    float* __restrict__ out, int n)
{
    __shared__ float w[64];
    if (threadIdx.x < 64) w[threadIdx.x] = Wr[threadIdx.x];
    __syncthreads();
    const float* h = g_h[in_idx];

    int gw = (blockIdx.x * blockDim.x + threadIdx.x) >> 5;
    if (gw >= n) return;
    int lane = threadIdx.x & 31;

    int start = g_rowptr[gw];
    int end = g_rowptr[gw + 1];
    float sum = 0.f;
    for (int j = start + lane; j < end; j += 32) sum += __ldg(&g_t[g_csr_src[j]]);

    float inv = 1.0f / (float)max(end - start, 1);
    float2 hv = *(const float2*)(h + (size_t)gw * 64 + 2 * lane);
    float2 wv = *(const float2*)&w[2 * lane];
    float v = sum * inv + hv.x * wv.x + hv.y * wv.y;
#pragma unroll
    for (int off = 16; off >= 1; off >>= 1) v += __shfl_xor_sync(0xffffffffu, v, off);

    if (lane == 0) {
        float z = v + bl[0];
        out[gw] = 1.0f / (1.0f + __expf(-z));
    }
}

// ---------------- launch ----------------
extern "C" void kernel_launch(void* const* d_in, const int* in_sizes, int n_in,
                              void* d_out, int out_size) {
    const float* x = (const float*)d_in[0];
    const void* ei = d_in[1];
    const float* Wl[5]; const float* bl[5]; const float* Wr[5];
    for (int i = 0; i < 5; i++) {
        Wl[i] = (const float*)d_in[2 + 3 * i];
        bl[i] = (const float*)d_in[3 + 3 * i];
        Wr[i] = (const float*)d_in[4 + 3 * i];
    }
    int n = in_sizes[0] / 13;
    int E = in_sizes[1] / 2;
    float* out = (float*)d_out;

    int eb = (E + 255) / 256;
    int nb = (n + 255) / 256;
    int fb13 = (n + 31) / 32;
    int fbtc = (n + TC_ROWS - 1) / TC_ROWS;
    int gb = (n * 16 + 255) / 256;     // 2 nodes per warp

    cudaFuncSetAttribute(fused64tc<false>, cudaFuncAttributeMaxDynamicSharedMemorySize, TC_DSMEM);
    cudaFuncSetAttribute(fused64tc<true>,  cudaFuncAttributeMaxDynamicSharedMemorySize, TC_DSMEM);

    detect_kernel<<<1, 1>>>((const int*)ei, E);
    count_kernel<<<eb, 256>>>(ei, E, n);
    scan_partial<<<nb, 256>>>(n);
    scan_bsum<<<1, 256>>>(nb, n);
    scan_final<<<nb, 256>>>(n);
    fill_kernel<<<eb, 256>>>(ei, E, n);

    fused13<<<fb13, 256>>>(x, Wl[0], bl[0], Wr[0], n);                                   // -> g_h[0]

    gather64<<<gb, 256>>>(0, n);
    fused64tc<false><<<fbtc, 256, TC_DSMEM>>>(0, 1, Wl[1], bl[1], Wr[1], Wl[1], n);      // h0 -> h1
    gather64<<<gb, 256>>>(1, n);
    fused64tc<false><<<fbtc, 256, TC_DSMEM>>>(1, 0, Wl[2], bl[2], Wr[2], Wl[2], n);      // h1 -> h0
    gather64<<<gb, 256>>>(0, n);
    fused64tc<true><<<fbtc, 256, TC_DSMEM>>>(0, 1, Wl[3], bl[3], Wr[3], Wl[4], n);       // h0 -> h1, t = h3 @ Wl4

    final_kernel<<<(n * 32 + 255) / 256, 256>>>(1, Wr[4], bl[4], out, n);
}

// round 15
// speedup vs baseline: 1.1861x; 1.0099x over previous
#include <cuda_runtime.h>
#include <cuda_fp16.h>
#include <cstdint>

#define NMAX 50000
#define EMAX 800000

// Scratch (device globals; no allocation allowed). Zero-initialized at load;
// every kernel_launch call leaves g_cnt zeroed (self-restoring invariant).
__device__ __align__(256) float   g_h[2][(size_t)NMAX * 64];
__device__ __align__(256) __half2 g_hh[2][(size_t)NMAX * 32];  // fp16 mirror for gather
__device__ __align__(256) float   g_agg[(size_t)NMAX * 64];
__device__ __align__(256) int     g_cnt[NMAX];
__device__ __align__(256) int     g_fill[NMAX];
__device__ __align__(256) int     g_rowptr[NMAX + 1];
__device__ __align__(256) int     g_csr_src[EMAX];
__device__ __align__(256) float   g_t[NMAX];
__device__ __align__(256) int     g_bsum[256];
__device__ int g_is64;

// ---------------- mma.sync tf32 helpers (compute_100-safe, sm_80+) ----------------
__device__ __forceinline__ uint32_t f2tf32(float x) {
    uint32_t r;
    asm("cvt.rna.tf32.f32 %0, %1;" : "=r"(r) : "f"(x));
    return r;
}
__device__ __forceinline__ void mma_tf32(float& d0, float& d1, float& d2, float& d3,
                                         uint32_t a0, uint32_t a1, uint32_t a2, uint32_t a3,
                                         uint32_t b0, uint32_t b1) {
    asm volatile(
        "mma.sync.aligned.m16n8k8.row.col.f32.tf32.tf32.f32 "
        "{%0,%1,%2,%3}, {%4,%5,%6,%7}, {%8,%9}, {%0,%1,%2,%3};"
        : "+f"(d0), "+f"(d1), "+f"(d2), "+f"(d3)
        : "r"(a0), "r"(a1), "r"(a2), "r"(a3), "r"(b0), "r"(b1));
}

// ---------------- edge dtype detection ----------------
__global__ void detect_kernel(const int* ei32, int E) {
    int all0 = 1;
    for (int k = 0; k < 64; k++) {
        long long p = 1 + 2 * ((long long)k * (E / 2 - 1) / 64);
        if (ei32[p] != 0) { all0 = 0; break; }
    }
    g_is64 = all0;
}

__device__ __forceinline__ int load_idx(const void* ei, int E, int half, int e, int is64, int n) {
    int v;
    if (is64) v = (int)((const long long*)ei)[(size_t)half * E + e];
    else      v = ((const int*)ei)[(size_t)half * E + e];
    return min(max(v, 0), n - 1);
}

// relies on g_cnt == 0 at entry (zero-init at load; re-zeroed by scan_final)
__global__ void count_kernel(const void* __restrict__ ei, int E, int n) {
    int e = blockIdx.x * blockDim.x + threadIdx.x;
    if (e >= E) return;
    int d = load_idx(ei, E, 1, e, g_is64, n);
    atomicAdd(&g_cnt[d], 1);
}

// ---------------- 2-phase parallel exclusive scan ----------------
__global__ void __launch_bounds__(256) scan_partial(int n) {
    int t = threadIdx.x;
    int i = blockIdx.x * 256 + t;
    int v = (i < n) ? g_cnt[i] : 0;
    int w = v;
#pragma unroll
    for (int off = 16; off >= 1; off >>= 1) w += __shfl_xor_sync(0xffffffffu, w, off);
    __shared__ int red[8];
    if ((t & 31) == 0) red[t >> 5] = w;
    __syncthreads();
    if (t == 0) {
        int s = 0;
#pragma unroll
        for (int k = 0; k < 8; k++) s += red[k];
        g_bsum[blockIdx.x] = s;
    }
}

// Each block redundantly scans the <=256 block sums in smem (removes scan_bsum launch),
// then does the block-local scan. Also seeds g_fill = rowptr and re-zeroes g_cnt.
__global__ void __launch_bounds__(256) scan_final(int nb, int n) {
    __shared__ int sb[256];
    int t = threadIdx.x;
    int lane = t & 31;
    int wid = t >> 5;

    sb[t] = (t < nb) ? g_bsum[t] : 0;
    __syncthreads();
#pragma unroll
    for (int off = 1; off < 256; off <<= 1) {
        int a = sb[t];
        int b = (t >= off) ? sb[t - off] : 0;
        __syncthreads();
        sb[t] = a + b;
        __syncthreads();
    }
    int prefix = (blockIdx.x == 0) ? 0 : sb[blockIdx.x - 1];
    int total = sb[nb - 1];

    int i = blockIdx.x * 256 + t;
    int v = (i < n) ? g_cnt[i] : 0;
    int inc = v;
#pragma unroll
    for (int off = 1; off < 32; off <<= 1) {
        int u = __shfl_up_sync(0xffffffffu, inc, off);
        if (lane >= off) inc += u;
    }
    __shared__ int wsum[8];
    if (lane == 31) wsum[wid] = inc;
    __syncthreads();
    if (t == 0) {
        int s = 0;
#pragma unroll
        for (int k = 0; k < 8; k++) { int u = wsum[k]; wsum[k] = s; s += u; }
    }
    __syncthreads();
    if (i < n) {
        int start = prefix + wsum[wid] + inc - v;
        g_rowptr[i] = start;
        g_fill[i] = start;
        g_cnt[i] = 0;
        if (i == n - 1) g_rowptr[n] = total;
    }
}

__global__ void fill_kernel(const void* __restrict__ ei, int E, int n) {
    int e = blockIdx.x * blockDim.x + threadIdx.x;
    if (e >= E) return;
    int is64 = g_is64;
    int s = load_idx(ei, E, 0, e, is64, n);
    int d = load_idx(ei, E, 1, e, is64, n);
    int pos = atomicAdd(&g_fill[d], 1);
    if (pos < EMAX) g_csr_src[pos] = s;
}

// ---------------- Gather: two nodes per warp, fp16 rows (128B), fp32 accumulate ------
// Each half-warp owns one node: 16 lanes x LDG.64 = full 128B fp16 row per edge.
// Each lane owns 4 columns; accumulates in fp32; writes fp32 agg (no cross-lane reduce).
__global__ void __launch_bounds__(256, 4) gather64(int in_idx, int n) {
    const __half2* hin = g_hh[in_idx];
    int gwarp = (blockIdx.x * blockDim.x + threadIdx.x) >> 5;
    int lane = threadIdx.x & 31;
    int half = lane >> 4;
    int lane16 = lane & 15;
    uint32_t hmask = half ? 0xffff0000u : 0x0000ffffu;

    int node = gwarp * 2 + half;
    int start = 0, end = 0;
    if (node < n) { start = g_rowptr[node]; end = g_rowptr[node + 1]; }

    float4 acc = make_float4(0.f, 0.f, 0.f, 0.f);
    for (int j = start; j < end; j += 16) {
        int m = min(16, end - j);
        int eid = (lane16 < m) ? g_csr_src[j + lane16] : 0;
#pragma unroll
        for (int k = 0; k < 16; k += 8) {
            if (k >= m) break;
            uint2 raw[8];
#pragma unroll
            for (int u = 0; u < 8; u++) {
                int idx = k + u;
                int s = __shfl_sync(hmask, eid, idx, 16);
                if (idx < m)
                    raw[u] = *(const uint2*)(hin + (size_t)s * 32 + lane16 * 2);
                else
                    raw[u] = make_uint2(0u, 0u);
            }
#pragma unroll
            for (int u = 0; u < 8; u++) {
                float2 f0 = __half22float2(*(__half2*)&raw[u].x);
                float2 f1 = __half22float2(*(__half2*)&raw[u].y);
                acc.x += f0.x; acc.y += f0.y; acc.z += f1.x; acc.w += f1.y;
            }
        }
    }
    if (node < n) {
        float inv = 1.0f / (float)max(end - start, 1);
        acc.x *= inv; acc.y *= inv; acc.z *= inv; acc.w *= inv;
        *(float4*)&g_agg[(size_t)node * 64 + lane16 * 4] = acc;
    }
}

// ---------------- Layer GEMM: load agg+h -> smem, tf32 mma (3xTF32) ----------------
// Epilogue writes fp32 hout AND fp16 mirror for the next gather.
#define TC_ROWS 64
#define TC_LA 132
#define TC_DSMEM (2 * 64 * TC_LA * 4)

template <bool FT>
__global__ void __launch_bounds__(256, 3) fused64tc(
    int in_idx, int out_idx,
    const float* __restrict__ Wl, const float* __restrict__ bl,
    const float* __restrict__ Wr, const float* __restrict__ Wl4,
    int n)
{
    extern __shared__ __align__(16) float dyn[];
    float* a_s = dyn;                 // 64 x 132
    float* b_s = a_s + 64 * TC_LA;    // 64 x 132 (n-major: b_s[nn][kk])
    __shared__ float bl_s[64];
    __shared__ float wl4_s[64];
    __shared__ float s_p[64];

    const float* hin = g_h[in_idx];
    float* hout = g_h[out_idx];
    __half2* hhout = g_hh[out_idx];

    int tid = threadIdx.x;
    int base = blockIdx.x * TC_ROWS;
    int warp = tid >> 5;
    int lane = tid & 31;

    for (int i = tid; i < 64 * 128; i += 256) {
        int nn = i & 63;
        int kk = i >> 6;
        float v = (kk < 64) ? Wl[kk * 64 + nn] : Wr[(kk - 64) * 64 + nn];
        b_s[nn * TC_LA + kk] = v;
    }
    if (tid < 64) {
        bl_s[tid] = bl[tid];
        if (FT) wl4_s[tid] = Wl4[tid];
    }

    for (int i = tid; i < 64 * 16; i += 256) {
        int r = i >> 4;
        int c4 = i & 15;
        int row = base + r;
        float4 av = make_float4(0.f, 0.f, 0.f, 0.f);
        float4 hv = make_float4(0.f, 0.f, 0.f, 0.f);
        if (row < n) {
            av = *(const float4*)&g_agg[(size_t)row * 64 + c4 * 4];
            hv = *(const float4*)(hin + (size_t)row * 64 + c4 * 4);
        }
        *(float4*)&a_s[r * TC_LA + c4 * 4] = av;
        *(float4*)&a_s[r * TC_LA + 64 + c4 * 4] = hv;
    }
    __syncthreads();

    int wr = warp & 3;
    int wc = warp >> 2;
    int g = lane >> 2;
    int t4 = lane & 3;
    int ar0 = wr * 16 + g;

    float d[4][4];
#pragma unroll
    for (int nt = 0; nt < 4; nt++)
#pragma unroll
        for (int c = 0; c < 4; c++) d[nt][c] = 0.f;

#pragma unroll
    for (int ks = 0; ks < 16; ks++) {
        int k0 = ks * 8;
        float af[4];
        af[0] = a_s[ar0 * TC_LA + k0 + t4];
        af[1] = a_s[(ar0 + 8) * TC_LA + k0 + t4];
        af[2] = a_s[ar0 * TC_LA + k0 + t4 + 4];
        af[3] = a_s[(ar0 + 8) * TC_LA + k0 + t4 + 4];
        uint32_t ah[4], al[4];
#pragma unroll
        for (int i = 0; i < 4; i++) {
            ah[i] = f2tf32(af[i]);
            al[i] = f2tf32(af[i] - __uint_as_float(ah[i]));
        }
#pragma unroll
        for (int nt = 0; nt < 4; nt++) {
            int nn = wc * 32 + nt * 8 + g;
            float bf0 = b_s[nn * TC_LA + k0 + t4];
            float bf1 = b_s[nn * TC_LA + k0 + t4 + 4];
            uint32_t bh0 = f2tf32(bf0), bh1 = f2tf32(bf1);
            uint32_t bl0 = f2tf32(bf0 - __uint_as_float(bh0));
            uint32_t bl1 = f2tf32(bf1 - __uint_as_float(bh1));
            mma_tf32(d[nt][0], d[nt][1], d[nt][2], d[nt][3], ah[0], ah[1], ah[2], ah[3], bh0, bh1);
            mma_tf32(d[nt][0], d[nt][1], d[nt][2], d[nt][3], al[0], al[1], al[2], al[3], bh0, bh1);
            mma_tf32(d[nt][0], d[nt][1], d[nt][2], d[nt][3], ah[0], ah[1], ah[2], ah[3], bl0, bl1);
        }
    }

    int row0 = base + wr * 16 + g;
    int row1 = row0 + 8;
    float p0 = 0.f, p1 = 0.f;
#pragma unroll
    for (int nt = 0; nt < 4; nt++) {
        int c = wc * 32 + nt * 8 + 2 * t4;
        float v0 = fmaxf(d[nt][0] + bl_s[c], 0.f);
        float v1 = fmaxf(d[nt][1] + bl_s[c + 1], 0.f);
        float v2 = fmaxf(d[nt][2] + bl_s[c], 0.f);
        float v3 = fmaxf(d[nt][3] + bl_s[c + 1], 0.f);
        if (row0 < n) {
            *(float2*)(hout + (size_t)row0 * 64 + c) = make_float2(v0, v1);
            hhout[(size_t)row0 * 32 + (c >> 1)] = __floats2half2_rn(v0, v1);
        }
        if (row1 < n) {
            *(float2*)(hout + (size_t)row1 * 64 + c) = make_float2(v2, v3);
            hhout[(size_t)row1 * 32 + (c >> 1)] = __floats2half2_rn(v2, v3);
        }
        if (FT) {
            p0 += v0 * wl4_s[c] + v1 * wl4_s[c + 1];
            p1 += v2 * wl4_s[c] + v3 * wl4_s[c + 1];
        }
    }

    if (FT) {
        p0 += __shfl_xor_sync(0xffffffffu, p0, 1);
        p0 += __shfl_xor_sync(0xffffffffu, p0, 2);
        p1 += __shfl_xor_sync(0xffffffffu, p1, 1);
        p1 += __shfl_xor_sync(0xffffffffu, p1, 2);
        int r0 = wr * 16 + g;
        if (wc == 0 && t4 == 0) { s_p[r0] = p0; s_p[r0 + 8] = p1; }
        __syncthreads();
        if (wc == 1 && t4 == 0) {
            if (row0 < n) g_t[row0] = p0 + s_p[r0];
            if (row1 < n) g_t[row1] = p1 + s_p[r0 + 8];
        }
    }
}

// ---------------- Fused layer 0: CIN=13 (FFMA path); writes fp32 + fp16 mirror -------
__global__ void __launch_bounds__(256) fused13(
    const float* __restrict__ x,
    const float* __restrict__ Wl, const float* __restrict__ bl,
    const float* __restrict__ Wr, int n)
{
    constexpr int ROWS = 32;
    constexpr int L = 28;
    __shared__ __align__(16) float w_s[2 * 13 * 64];
    __shared__ __align__(16) float in_s[ROWS * L];
    __shared__ float bl_s[64];

    float* hout = g_h[0];
    __half2* hhout = g_hh[0];
    int tid = threadIdx.x;
    int base = blockIdx.x * ROWS;
    int warp = tid >> 5;
    int lane = tid & 31;

    for (int i = tid; i < 2 * 13 * 64; i += 256) w_s[i] = (i < 13 * 64) ? Wl[i] : Wr[i - 13 * 64];
    if (tid < 64) bl_s[tid] = bl[tid];

    for (int q = 0; q < 4; q++) {
        int r = warp * 4 + q;
        int row = base + r;
        float acc = 0.f;
        if (row < n) {
            int start = g_rowptr[row];
            int end = g_rowptr[row + 1];
            for (int j = start; j < end; j += 32) {
                int m = min(32, end - j);
                int eid = (lane < m) ? g_csr_src[j + lane] : 0;
#pragma unroll
                for (int k = 0; k < 32; k += 8) {
                    if (k >= m) break;
                    float v[8];
#pragma unroll
                    for (int u = 0; u < 8; u++) {
                        int s = __shfl_sync(0xffffffffu, eid, k + u);
                        v[u] = (lane < 13 && k + u < m) ? __ldg(&x[(size_t)s * 13 + lane]) : 0.f;
                    }
#pragma unroll
                    for (int u = 0; u < 8; u++) acc += v[u];
                }
            }
            float inv = 1.0f / (float)max(end - start, 1);
            if (lane < 13) {
                in_s[r * L + lane] = acc * inv;
                in_s[r * L + 14 + lane] = __ldg(&x[(size_t)row * 13 + lane]);
            }
        } else if (lane < 13) {
            in_s[r * L + lane] = 0.f;
            in_s[r * L + 14 + lane] = 0.f;
        }
    }
    __syncthreads();

    int rr = tid >> 4;
    int cg = tid & 15;
    int j0 = cg * 4;
    const float4* w4 = (const float4*)w_s;

    float a0[4], a1[4];
#pragma unroll
    for (int c = 0; c < 4; c++) { a0[c] = bl_s[j0 + c]; a1[c] = bl_s[j0 + c]; }

    const float* r0p = &in_s[rr * L];
    const float* r1p = &in_s[(rr + 16) * L];
#pragma unroll
    for (int k = 0; k < 13; k++) {
        float4 w = w4[k * 16 + cg];
        float x0 = r0p[k], x1 = r1p[k];
        a0[0] += x0 * w.x; a0[1] += x0 * w.y; a0[2] += x0 * w.z; a0[3] += x0 * w.w;
        a1[0] += x1 * w.x; a1[1] += x1 * w.y; a1[2] += x1 * w.z; a1[3] += x1 * w.w;
    }
#pragma unroll
    for (int k = 0; k < 13; k++) {
        float4 w = w4[(13 + k) * 16 + cg];
        float x0 = r0p[14 + k], x1 = r1p[14 + k];
        a0[0] += x0 * w.x; a0[1] += x0 * w.y; a0[2] += x0 * w.z; a0[3] += x0 * w.w;
        a1[0] += x1 * w.x; a1[1] += x1 * w.y; a1[2] += x1 * w.z; a1[3] += x1 * w.w;
    }

    int row0 = base + rr;
    int row1 = base + rr + 16;
    if (row0 < n) {
#pragma unroll
        for (int c = 0; c < 4; c++) a0[c] = fmaxf(a0[c], 0.f);
        *(float4*)(hout + (size_t)row0 * 64 + j0) = make_float4(a0[0], a0[1], a0[2], a0[3]);
        hhout[(size_t)row0 * 32 + (j0 >> 1)] = __floats2half2_rn(a0[0], a0[1]);
        hhout[(size_t)row0 * 32 + (j0 >> 1) + 1] = __floats2half2_rn(a0[2], a0[3]);
    }
    if (row1 < n) {
#pragma unroll
        for (int c = 0; c < 4; c++) a1[c] = fmaxf(a1[c], 0.f);
        *(float4*)(hout + (size_t)row1 * 64 + j0) = make_float4(a1[0], a1[1], a1[2], a1[3]);
        hhout[(size_t)row1 * 32 + (j0 >> 1)] = __floats2half2_rn(a1[0], a1[1]);
        hhout[(size_t)row1 * 32 + (j0 >> 1) + 1] = __floats2half2_rn(a1[2], a1[3]);
    }
}

// ---------------- Final layer (64 -> 1) ----------------
__global__ void __launch_bounds__(256) final_kernel(
    int in_idx,
    const float* __restrict__ Wr,
    const float* __restrict__ bl,
    float* __restrict__ out, int n)
{
    __shared__ float w[64];
    if (threadIdx.x < 64) w[threadIdx.x] = Wr[threadIdx.x];
    __syncthreads();
    const float* h = g_h[in_idx];

    int gw = (blockIdx.x * blockDim.x + threadIdx.x) >> 5;
    if (gw >= n) return;
    int lane = threadIdx.x & 31;

    int start = g_rowptr[gw];
    int end = g_rowptr[gw + 1];
    float sum = 0.f;
    for (int j = start + lane; j < end; j += 32) sum += __ldg(&g_t[g_csr_src[j]]);

    float inv = 1.0f / (float)max(end - start, 1);
    float2 hv = *(const float2*)(h + (size_t)gw * 64 + 2 * lane);
    float2 wv = *(const float2*)&w[2 * lane];
    float v = sum * inv + hv.x * wv.x + hv.y * wv.y;
#pragma unroll
    for (int off = 16; off >= 1; off >>= 1) v += __shfl_xor_sync(0xffffffffu, v, off);

    if (lane == 0) {
        float z = v + bl[0];
        out[gw] = 1.0f / (1.0f + __expf(-z));
    }
}

// ---------------- launch ----------------
extern "C" void kernel_launch(void* const* d_in, const int* in_sizes, int n_in,
                              void* d_out, int out_size) {
    const float* x = (const float*)d_in[0];
    const void* ei = d_in[1];
    const float* Wl[5]; const float* bl[5]; const float* Wr[5];
    for (int i = 0; i < 5; i++) {
        Wl[i] = (const float*)d_in[2 + 3 * i];
        bl[i] = (const float*)d_in[3 + 3 * i];
        Wr[i] = (const float*)d_in[4 + 3 * i];
    }
    int n = in_sizes[0] / 13;
    int E = in_sizes[1] / 2;
    float* out = (float*)d_out;

    int eb = (E + 255) / 256;
    int nb = (n + 255) / 256;
    int fb13 = (n + 31) / 32;
    int fbtc = (n + TC_ROWS - 1) / TC_ROWS;
    int gb = (n * 16 + 255) / 256;     // 2 nodes per warp

    cudaFuncSetAttribute(fused64tc<false>, cudaFuncAttributeMaxDynamicSharedMemorySize, TC_DSMEM);
    cudaFuncSetAttribute(fused64tc<true>,  cudaFuncAttributeMaxDynamicSharedMemorySize, TC_DSMEM);

    detect_kernel<<<1, 1>>>((const int*)ei, E);
    count_kernel<<<eb, 256>>>(ei, E, n);
    scan_partial<<<nb, 256>>>(n);
    scan_final<<<nb, 256>>>(nb, n);
    fill_kernel<<<eb, 256>>>(ei, E, n);

    fused13<<<fb13, 256>>>(x, Wl[0], bl[0], Wr[0], n);                                   // -> g_h[0] + g_hh[0]

    gather64<<<gb, 256>>>(0, n);
    fused64tc<false><<<fbtc, 256, TC_DSMEM>>>(0, 1, Wl[1], bl[1], Wr[1], Wl[1], n);      // h0 -> h1
    gather64<<<gb, 256>>>(1, n);
    fused64tc<false><<<fbtc, 256, TC_DSMEM>>>(1, 0, Wl[2], bl[2], Wr[2], Wl[2], n);      // h1 -> h0
    gather64<<<gb, 256>>>(0, n);
    fused64tc<true><<<fbtc, 256, TC_DSMEM>>>(0, 1, Wl[3], bl[3], Wr[3], Wl[4], n);       // h0 -> h1, t = h3 @ Wl4

    final_kernel<<<(n * 32 + 255) / 256, 256>>>(1, Wr[4], bl[4], out, n);
}

// round 16
// speedup vs baseline: 1.2083x; 1.0187x over previous
#include <cuda_runtime.h>
#include <cuda_fp16.h>
#include <cstdint>

#define NMAX 50000
#define EMAX 800000

// Scratch (device globals; no allocation allowed). Zero-initialized at load;
// every kernel_launch call leaves g_cnt zeroed (self-restoring invariant).
__device__ __align__(256) float   g_h[2][(size_t)NMAX * 64];
__device__ __align__(256) __half2 g_hh[2][(size_t)NMAX * 32];  // fp16 mirror for gather
__device__ __align__(256) float   g_agg[(size_t)NMAX * 64];
__device__ __align__(256) int     g_cnt[NMAX];
__device__ __align__(256) int     g_fill[NMAX];
__device__ __align__(256) int     g_rowptr[NMAX + 1];
__device__ __align__(256) int     g_csr_src[EMAX];
__device__ __align__(256) float   g_t[NMAX];
__device__ __align__(256) int     g_bsum[256];
__device__ int g_is64;

// ---------------- mma.sync tf32 helpers (compute_100-safe, sm_80+) ----------------
__device__ __forceinline__ uint32_t f2tf32(float x) {
    uint32_t r;
    asm("cvt.rna.tf32.f32 %0, %1;" : "=r"(r) : "f"(x));
    return r;
}
__device__ __forceinline__ void mma_tf32(float& d0, float& d1, float& d2, float& d3,
                                         uint32_t a0, uint32_t a1, uint32_t a2, uint32_t a3,
                                         uint32_t b0, uint32_t b1) {
    asm volatile(
        "mma.sync.aligned.m16n8k8.row.col.f32.tf32.tf32.f32 "
        "{%0,%1,%2,%3}, {%4,%5,%6,%7}, {%8,%9}, {%0,%1,%2,%3};"
        : "+f"(d0), "+f"(d1), "+f"(d2), "+f"(d3)
        : "r"(a0), "r"(a1), "r"(a2), "r"(a3), "r"(b0), "r"(b1));
}

// ---------------- edge dtype detection (parallel: 64 lanes, ballot) ----------------
__global__ void detect_kernel(const int* ei32, int E) {
    int t = threadIdx.x;               // 64 threads
    long long p = 1 + 2 * ((long long)t * (E / 2 - 1) / 64);
    int nz = (ei32[p] != 0) ? 1 : 0;
    unsigned b0 = __ballot_sync(0xffffffffu, (t < 32) ? nz : 0);
    __shared__ unsigned s_hi;
    if (t == 32) s_hi = 0;
    __syncthreads();
    unsigned bh = __ballot_sync(0xffffffffu, (t >= 32) ? nz : 0);
    if (t == 32) s_hi = bh;
    __syncthreads();
    if (t == 0) g_is64 = (b0 == 0 && s_hi == 0) ? 1 : 0;
}

__device__ __forceinline__ int load_idx(const void* ei, int E, int half, int e, int is64, int n) {
    int v;
    if (is64) v = (int)((const long long*)ei)[(size_t)half * E + e];
    else      v = ((const int*)ei)[(size_t)half * E + e];
    return min(max(v, 0), n - 1);
}

// relies on g_cnt == 0 at entry (zero-init at load; re-zeroed by scan_final)
__global__ void count_kernel(const void* __restrict__ ei, int E, int n) {
    int e = blockIdx.x * blockDim.x + threadIdx.x;
    if (e >= E) return;
    int d = load_idx(ei, E, 1, e, g_is64, n);
    atomicAdd(&g_cnt[d], 1);
}

// ---------------- 2-phase parallel exclusive scan ----------------
__global__ void __launch_bounds__(256) scan_partial(int n) {
    int t = threadIdx.x;
    int i = blockIdx.x * 256 + t;
    int v = (i < n) ? g_cnt[i] : 0;
    int w = v;
#pragma unroll
    for (int off = 16; off >= 1; off >>= 1) w += __shfl_xor_sync(0xffffffffu, w, off);
    __shared__ int red[8];
    if ((t & 31) == 0) red[t >> 5] = w;
    __syncthreads();
    if (t == 0) {
        int s = 0;
#pragma unroll
        for (int k = 0; k < 8; k++) s += red[k];
        g_bsum[blockIdx.x] = s;
    }
}

// Each block redundantly scans the <=256 block sums in smem, then block-local scan.
// Seeds g_fill = rowptr and re-zeroes g_cnt.
__global__ void __launch_bounds__(256) scan_final(int nb, int n) {
    __shared__ int sb[256];
    int t = threadIdx.x;
    int lane = t & 31;
    int wid = t >> 5;

    sb[t] = (t < nb) ? g_bsum[t] : 0;
    __syncthreads();
#pragma unroll
    for (int off = 1; off < 256; off <<= 1) {
        int a = sb[t];
        int b = (t >= off) ? sb[t - off] : 0;
        __syncthreads();
        sb[t] = a + b;
        __syncthreads();
    }
    int prefix = (blockIdx.x == 0) ? 0 : sb[blockIdx.x - 1];
    int total = sb[nb - 1];

    int i = blockIdx.x * 256 + t;
    int v = (i < n) ? g_cnt[i] : 0;
    int inc = v;
#pragma unroll
    for (int off = 1; off < 32; off <<= 1) {
        int u = __shfl_up_sync(0xffffffffu, inc, off);
        if (lane >= off) inc += u;
    }
    __shared__ int wsum[8];
    if (lane == 31) wsum[wid] = inc;
    __syncthreads();
    if (t == 0) {
        int s = 0;
#pragma unroll
        for (int k = 0; k < 8; k++) { int u = wsum[k]; wsum[k] = s; s += u; }
    }
    __syncthreads();
    if (i < n) {
        int start = prefix + wsum[wid] + inc - v;
        g_rowptr[i] = start;
        g_fill[i] = start;
        g_cnt[i] = 0;
        if (i == n - 1) g_rowptr[n] = total;
    }
}

__global__ void fill_kernel(const void* __restrict__ ei, int E, int n) {
    int e = blockIdx.x * blockDim.x + threadIdx.x;
    if (e >= E) return;
    int is64 = g_is64;
    int s = load_idx(ei, E, 0, e, is64, n);
    int d = load_idx(ei, E, 1, e, is64, n);
    int pos = atomicAdd(&g_fill[d], 1);
    if (pos < EMAX) g_csr_src[pos] = s;
}

// ---------------- Gather: FOUR nodes per warp (8 lanes each), fp16 rows --------------
// Quarter-warp owns one node: 8 lanes x LDG.128 = full 128B fp16 row per edge.
// 8 edges unrolled -> 8 warp-LDG.128 in flight = 4KB outstanding per warp.
// Each lane owns 8 columns; fp32 accumulate; writes 2x float4 (no cross-lane reduce).
__global__ void __launch_bounds__(256, 4) gather64(int in_idx, int n) {
    const uint4* hin = (const uint4*)g_hh[in_idx];   // 8 x uint4 per row
    int gwarp = (blockIdx.x * blockDim.x + threadIdx.x) >> 5;
    int lane = threadIdx.x & 31;
    int q = lane >> 3;
    int lane8 = lane & 7;
    uint32_t qmask = 0xffu << (q * 8);

    int node = gwarp * 4 + q;
    int start = 0, end = 0;
    if (node < n) { start = g_rowptr[node]; end = g_rowptr[node + 1]; }

    float acc[8];
#pragma unroll
    for (int c = 0; c < 8; c++) acc[c] = 0.f;

    for (int j = start; j < end; j += 8) {
        int m = min(8, end - j);
        int eid = (lane8 < m) ? g_csr_src[j + lane8] : 0;
        uint4 v[8];
#pragma unroll
        for (int u = 0; u < 8; u++) {
            int s = __shfl_sync(qmask, eid, u, 8);
            if (u < m)
                v[u] = hin[(size_t)s * 8 + lane8];
            else
                v[u] = make_uint4(0u, 0u, 0u, 0u);
        }
#pragma unroll
        for (int u = 0; u < 8; u++) {
            float2 f0 = __half22float2(*(__half2*)&v[u].x);
            float2 f1 = __half22float2(*(__half2*)&v[u].y);
            float2 f2 = __half22float2(*(__half2*)&v[u].z);
            float2 f3 = __half22float2(*(__half2*)&v[u].w);
            acc[0] += f0.x; acc[1] += f0.y; acc[2] += f1.x; acc[3] += f1.y;
            acc[4] += f2.x; acc[5] += f2.y; acc[6] += f3.x; acc[7] += f3.y;
        }
    }
    if (node < n) {
        float inv = 1.0f / (float)max(end - start, 1);
#pragma unroll
        for (int c = 0; c < 8; c++) acc[c] *= inv;
        float* o = &g_agg[(size_t)node * 64 + lane8 * 8];
        *(float4*)o = make_float4(acc[0], acc[1], acc[2], acc[3]);
        *(float4*)(o + 4) = make_float4(acc[4], acc[5], acc[6], acc[7]);
    }
}

// ---------------- Layer GEMM: load agg+h -> smem, tf32 mma (3xTF32) ----------------
// Epilogue writes fp32 hout AND fp16 mirror for the next gather.
#define TC_ROWS 64
#define TC_LA 132
#define TC_DSMEM (2 * 64 * TC_LA * 4)

template <bool FT>
__global__ void __launch_bounds__(256, 3) fused64tc(
    int in_idx, int out_idx,
    const float* __restrict__ Wl, const float* __restrict__ bl,
    const float* __restrict__ Wr, const float* __restrict__ Wl4,
    int n)
{
    extern __shared__ __align__(16) float dyn[];
    float* a_s = dyn;                 // 64 x 132
    float* b_s = a_s + 64 * TC_LA;    // 64 x 132 (n-major: b_s[nn][kk])
    __shared__ float bl_s[64];
    __shared__ float wl4_s[64];
    __shared__ float s_p[64];

    const float* hin = g_h[in_idx];
    float* hout = g_h[out_idx];
    __half2* hhout = g_hh[out_idx];

    int tid = threadIdx.x;
    int base = blockIdx.x * TC_ROWS;
    int warp = tid >> 5;
    int lane = tid & 31;

    for (int i = tid; i < 64 * 128; i += 256) {
        int nn = i & 63;
        int kk = i >> 6;
        float v = (kk < 64) ? Wl[kk * 64 + nn] : Wr[(kk - 64) * 64 + nn];
        b_s[nn * TC_LA + kk] = v;
    }
    if (tid < 64) {
        bl_s[tid] = bl[tid];
        if (FT) wl4_s[tid] = Wl4[tid];
    }

    for (int i = tid; i < 64 * 16; i += 256) {
        int r = i >> 4;
        int c4 = i & 15;
        int row = base + r;
        float4 av = make_float4(0.f, 0.f, 0.f, 0.f);
        float4 hv = make_float4(0.f, 0.f, 0.f, 0.f);
        if (row < n) {
            av = *(const float4*)&g_agg[(size_t)row * 64 + c4 * 4];
            hv = *(const float4*)(hin + (size_t)row * 64 + c4 * 4);
        }
        *(float4*)&a_s[r * TC_LA + c4 * 4] = av;
        *(float4*)&a_s[r * TC_LA + 64 + c4 * 4] = hv;
    }
    __syncthreads();

    int wr = warp & 3;
    int wc = warp >> 2;
    int g = lane >> 2;
    int t4 = lane & 3;
    int ar0 = wr * 16 + g;

    float d[4][4];
#pragma unroll
    for (int nt = 0; nt < 4; nt++)
#pragma unroll
        for (int c = 0; c < 4; c++) d[nt][c] = 0.f;

#pragma unroll
    for (int ks = 0; ks < 16; ks++) {
        int k0 = ks * 8;
        float af[4];
        af[0] = a_s[ar0 * TC_LA + k0 + t4];
        af[1] = a_s[(ar0 + 8) * TC_LA + k0 + t4];
        af[2] = a_s[ar0 * TC_LA + k0 + t4 + 4];
        af[3] = a_s[(ar0 + 8) * TC_LA + k0 + t4 + 4];
        uint32_t ah[4], al[4];
#pragma unroll
        for (int i = 0; i < 4; i++) {
            ah[i] = f2tf32(af[i]);
            al[i] = f2tf32(af[i] - __uint_as_float(ah[i]));
        }
#pragma unroll
        for (int nt = 0; nt < 4; nt++) {
            int nn = wc * 32 + nt * 8 + g;
            float bf0 = b_s[nn * TC_LA + k0 + t4];
            float bf1 = b_s[nn * TC_LA + k0 + t4 + 4];
            uint32_t bh0 = f2tf32(bf0), bh1 = f2tf32(bf1);
            uint32_t bl0 = f2tf32(bf0 - __uint_as_float(bh0));
            uint32_t bl1 = f2tf32(bf1 - __uint_as_float(bh1));
            mma_tf32(d[nt][0], d[nt][1], d[nt][2], d[nt][3], ah[0], ah[1], ah[2], ah[3], bh0, bh1);
            mma_tf32(d[nt][0], d[nt][1], d[nt][2], d[nt][3], al[0], al[1], al[2], al[3], bh0, bh1);
            mma_tf32(d[nt][0], d[nt][1], d[nt][2], d[nt][3], ah[0], ah[1], ah[2], ah[3], bl0, bl1);
        }
    }

    int row0 = base + wr * 16 + g;
    int row1 = row0 + 8;
    float p0 = 0.f, p1 = 0.f;
#pragma unroll
    for (int nt = 0; nt < 4; nt++) {
        int c = wc * 32 + nt * 8 + 2 * t4;
        float v0 = fmaxf(d[nt][0] + bl_s[c], 0.f);
        float v1 = fmaxf(d[nt][1] + bl_s[c + 1], 0.f);
        float v2 = fmaxf(d[nt][2] + bl_s[c], 0.f);
        float v3 = fmaxf(d[nt][3] + bl_s[c + 1], 0.f);
        if (row0 < n) {
            *(float2*)(hout + (size_t)row0 * 64 + c) = make_float2(v0, v1);
            hhout[(size_t)row0 * 32 + (c >> 1)] = __floats2half2_rn(v0, v1);
        }
        if (row1 < n) {
            *(float2*)(hout + (size_t)row1 * 64 + c) = make_float2(v2, v3);
            hhout[(size_t)row1 * 32 + (c >> 1)] = __floats2half2_rn(v2, v3);
        }
        if (FT) {
            p0 += v0 * wl4_s[c] + v1 * wl4_s[c + 1];
            p1 += v2 * wl4_s[c] + v3 * wl4_s[c + 1];
        }
    }

    if (FT) {
        p0 += __shfl_xor_sync(0xffffffffu, p0, 1);
        p0 += __shfl_xor_sync(0xffffffffu, p0, 2);
        p1 += __shfl_xor_sync(0xffffffffu, p1, 1);
        p1 += __shfl_xor_sync(0xffffffffu, p1, 2);
        int r0 = wr * 16 + g;
        if (wc == 0 && t4 == 0) { s_p[r0] = p0; s_p[r0 + 8] = p1; }
        __syncthreads();
        if (wc == 1 && t4 == 0) {
            if (row0 < n) g_t[row0] = p0 + s_p[r0];
            if (row1 < n) g_t[row1] = p1 + s_p[r0 + 8];
        }
    }
}

// ---------------- Fused layer 0: CIN=13 (FFMA path); writes fp32 + fp16 mirror -------
__global__ void __launch_bounds__(256) fused13(
    const float* __restrict__ x,
    const float* __restrict__ Wl, const float* __restrict__ bl,
    const float* __restrict__ Wr, int n)
{
    constexpr int ROWS = 32;
    constexpr int L = 28;
    __shared__ __align__(16) float w_s[2 * 13 * 64];
    __shared__ __align__(16) float in_s[ROWS * L];
    __shared__ float bl_s[64];

    float* hout = g_h[0];
    __half2* hhout = g_hh[0];
    int tid = threadIdx.x;
    int base = blockIdx.x * ROWS;
    int warp = tid >> 5;
    int lane = tid & 31;

    for (int i = tid; i < 2 * 13 * 64; i += 256) w_s[i] = (i < 13 * 64) ? Wl[i] : Wr[i - 13 * 64];
    if (tid < 64) bl_s[tid] = bl[tid];

    for (int q = 0; q < 4; q++) {
        int r = warp * 4 + q;
        int row = base + r;
        float acc = 0.f;
        if (row < n) {
            int start = g_rowptr[row];
            int end = g_rowptr[row + 1];
            for (int j = start; j < end; j += 32) {
                int m = min(32, end - j);
                int eid = (lane < m) ? g_csr_src[j + lane] : 0;
#pragma unroll
                for (int k = 0; k < 32; k += 8) {
                    if (k >= m) break;
                    float v[8];
#pragma unroll
                    for (int u = 0; u < 8; u++) {
                        int s = __shfl_sync(0xffffffffu, eid, k + u);
                        v[u] = (lane < 13 && k + u < m) ? __ldg(&x[(size_t)s * 13 + lane]) : 0.f;
                    }
#pragma unroll
                    for (int u = 0; u < 8; u++) acc += v[u];
                }
            }
            float inv = 1.0f / (float)max(end - start, 1);
            if (lane < 13) {
                in_s[r * L + lane] = acc * inv;
                in_s[r * L + 14 + lane] = __ldg(&x[(size_t)row * 13 + lane]);
            }
        } else if (lane < 13) {
            in_s[r * L + lane] = 0.f;
            in_s[r * L + 14 + lane] = 0.f;
        }
    }
    __syncthreads();

    int rr = tid >> 4;
    int cg = tid & 15;
    int j0 = cg * 4;
    const float4* w4 = (const float4*)w_s;

    float a0[4], a1[4];
#pragma unroll
    for (int c = 0; c < 4; c++) { a0[c] = bl_s[j0 + c]; a1[c] = bl_s[j0 + c]; }

    const float* r0p = &in_s[rr * L];
    const float* r1p = &in_s[(rr + 16) * L];
#pragma unroll
    for (int k = 0; k < 13; k++) {
        float4 w = w4[k * 16 + cg];
        float x0 = r0p[k], x1 = r1p[k];
        a0[0] += x0 * w.x; a0[1] += x0 * w.y; a0[2] += x0 * w.z; a0[3] += x0 * w.w;
        a1[0] += x1 * w.x; a1[1] += x1 * w.y; a1[2] += x1 * w.z; a1[3] += x1 * w.w;
    }
#pragma unroll
    for (int k = 0; k < 13; k++) {
        float4 w = w4[(13 + k) * 16 + cg];
        float x0 = r0p[14 + k], x1 = r1p[14 + k];
        a0[0] += x0 * w.x; a0[1] += x0 * w.y; a0[2] += x0 * w.z; a0[3] += x0 * w.w;
        a1[0] += x1 * w.x; a1[1] += x1 * w.y; a1[2] += x1 * w.z; a1[3] += x1 * w.w;
    }

    int row0 = base + rr;
    int row1 = base + rr + 16;
    if (row0 < n) {
#pragma unroll
        for (int c = 0; c < 4; c++) a0[c] = fmaxf(a0[c], 0.f);
        *(float4*)(hout + (size_t)row0 * 64 + j0) = make_float4(a0[0], a0[1], a0[2], a0[3]);
        hhout[(size_t)row0 * 32 + (j0 >> 1)] = __floats2half2_rn(a0[0], a0[1]);
        hhout[(size_t)row0 * 32 + (j0 >> 1) + 1] = __floats2half2_rn(a0[2], a0[3]);
    }
    if (row1 < n) {
#pragma unroll
        for (int c = 0; c < 4; c++) a1[c] = fmaxf(a1[c], 0.f);
        *(float4*)(hout + (size_t)row1 * 64 + j0) = make_float4(a1[0], a1[1], a1[2], a1[3]);
        hhout[(size_t)row1 * 32 + (j0 >> 1)] = __floats2half2_rn(a1[0], a1[1]);
        hhout[(size_t)row1 * 32 + (j0 >> 1) + 1] = __floats2half2_rn(a1[2], a1[3]);
    }
}

// ---------------- Final layer (64 -> 1) ----------------
__global__ void __launch_bounds__(256) final_kernel(
    int in_idx,
    const float* __restrict__ Wr,
    const float* __restrict__ bl,
    float* __restrict__ out, int n)
{
    __shared__ float w[64];
    if (threadIdx.x < 64) w[threadIdx.x] = Wr[threadIdx.x];
    __syncthreads();
    const float* h = g_h[in_idx];

    int gw = (blockIdx.x * blockDim.x + threadIdx.x) >> 5;
    if (gw >= n) return;
    int lane = threadIdx.x & 31;

    int start = g_rowptr[gw];
    int end = g_rowptr[gw + 1];
    float sum = 0.f;
    for (int j = start + lane; j < end; j += 32) sum += __ldg(&g_t[g_csr_src[j]]);

    float inv = 1.0f / (float)max(end - start, 1);
    float2 hv = *(const float2*)(h + (size_t)gw * 64 + 2 * lane);
    float2 wv = *(const float2*)&w[2 * lane];
    float v = sum * inv + hv.x * wv.x + hv.y * wv.y;
#pragma unroll
    for (int off = 16; off >= 1; off >>= 1) v += __shfl_xor_sync(0xffffffffu, v, off);

    if (lane == 0) {
        float z = v + bl[0];
        out[gw] = 1.0f / (1.0f + __expf(-z));
    }
}

// ---------------- launch ----------------
extern "C" void kernel_launch(void* const* d_in, const int* in_sizes, int n_in,
                              void* d_out, int out_size) {
    const float* x = (const float*)d_in[0];
    const void* ei = d_in[1];
    const float* Wl[5]; const float* bl[5]; const float* Wr[5];
    for (int i = 0; i < 5; i++) {
        Wl[i] = (const float*)d_in[2 + 3 * i];
        bl[i] = (const float*)d_in[3 + 3 * i];
        Wr[i] = (const float*)d_in[4 + 3 * i];
    }
    int n = in_sizes[0] / 13;
    int E = in_sizes[1] / 2;
    float* out = (float*)d_out;

    int eb = (E + 255) / 256;
    int nb = (n + 255) / 256;
    int fb13 = (n + 31) / 32;
    int fbtc = (n + TC_ROWS - 1) / TC_ROWS;
    int gb = (n * 8 + 255) / 256;      // 4 nodes per warp

    cudaFuncSetAttribute(fused64tc<false>, cudaFuncAttributeMaxDynamicSharedMemorySize, TC_DSMEM);
    cudaFuncSetAttribute(fused64tc<true>,  cudaFuncAttributeMaxDynamicSharedMemorySize, TC_DSMEM);

    detect_kernel<<<1, 64>>>((const int*)ei, E);
    count_kernel<<<eb, 256>>>(ei, E, n);
    scan_partial<<<nb, 256>>>(n);
    scan_final<<<nb, 256>>>(nb, n);
    fill_kernel<<<eb, 256>>>(ei, E, n);

    fused13<<<fb13, 256>>>(x, Wl[0], bl[0], Wr[0], n);                                   // -> g_h[0] + g_hh[0]

    gather64<<<gb, 256>>>(0, n);
    fused64tc<false><<<fbtc, 256, TC_DSMEM>>>(0, 1, Wl[1], bl[1], Wr[1], Wl[1], n);      // h0 -> h1
    gather64<<<gb, 256>>>(1, n);
    fused64tc<false><<<fbtc, 256, TC_DSMEM>>>(1, 0, Wl[2], bl[2], Wr[2], Wl[2], n);      // h1 -> h0
    gather64<<<gb, 256>>>(0, n);
    fused64tc<true><<<fbtc, 256, TC_DSMEM>>>(0, 1, Wl[3], bl[3], Wr[3], Wl[4], n);       // h0 -> h1, t = h3 @ Wl4

    final_kernel<<<(n * 32 + 255) / 256, 256>>>(1, Wr[4], bl[4], out, n);
}